// round 6
// baseline (speedup 1.0000x reference)
#include <cuda_runtime.h>

// Problem constants
#define H_   128
#define W_   128
#define C_   32
#define B_   4
#define OH_  120
#define OW_  120
#define OCH_ 100
#define F_   64

__device__ float g_offbuf[(size_t)B_ * OH_ * OW_ * OCH_];
// Pair-packed offset-conv weights: [k][c2][ch][2] = w_off[k, 2*c2+e, ch]
__device__ float g_wpack[25 * 16 * 100 * 2];   // 320 KB

// ---- packed f32x2 helpers (sm_103a FFMA2 path) ----------------------------
typedef unsigned long long u64t;

__device__ __forceinline__ u64t ffma2(u64t a, u64t b, u64t c) {
    u64t d;
    asm("fma.rn.f32x2 %0, %1, %2, %3;" : "=l"(d) : "l"(a), "l"(b), "l"(c));
    return d;
}
__device__ __forceinline__ u64t fmul2(u64t a, u64t b) {
    u64t d;
    asm("mul.rn.f32x2 %0, %1, %2;" : "=l"(d) : "l"(a), "l"(b));
    return d;
}
__device__ __forceinline__ u64t dup2(float x) {
    u64t d; unsigned xi = __float_as_uint(x);
    asm("mov.b64 %0, {%1, %1};" : "=l"(d) : "r"(xi));
    return d;
}
__device__ __forceinline__ float2 up2(u64t v) {
    float2 f;
    asm("mov.b64 {%0, %1}, %2;" : "=f"(f.x), "=f"(f.y) : "l"(v));
    return f;
}
union f4u { float4 f; ulonglong2 u; };

// ---------------------------------------------------------------------------
// Prepass: pack w_off (5,5,32,100) -> g_wpack[k][c2][ch][2]
// ---------------------------------------------------------------------------
__global__ void pack_woff_kernel(const float* __restrict__ w_off)
{
    int idx = blockIdx.x * 256 + threadIdx.x;
    if (idx >= 25 * 16 * 100 * 2) return;
    int e  = idx & 1;
    int r  = idx >> 1;
    int ch = r % 100;
    int t  = r / 100;
    int c2 = t % 16;
    int k  = t / 16;
    g_wpack[idx] = w_off[(k * 32 + 2 * c2 + e) * 100 + ch];
}

// ---------------------------------------------------------------------------
// Kernel A: dense dilated 5x5 conv -> 100 offset channels.
// Tile 8x8 px, 400 threads: tm=tid%25 (ch-quad), tn=tid/25 (px-quad, 16).
// FFMA2 packed over K-pairs: A operand = (w[c],w[c+1]) pairs from g_wpack
// (LDG.128), B operand = contiguous (c,c+1) patch pair (LDS.64, broadcast).
// Zero dup2 movs in the hot loop. One __syncthreads total.
// ---------------------------------------------------------------------------
#define PCOL 36
__global__ __launch_bounds__(400, 2)
void offset_conv_kernel(const float* __restrict__ vol,
                        const float* __restrict__ b_off)
{
    __shared__ float patch[16 * 16 * PCOL];  // 36.9 KB

    const int tid = threadIdx.x;
    const int ox0 = blockIdx.x * 8;
    const int oy0 = blockIdx.y * 8;
    const int b   = blockIdx.z;

    for (int idx = tid; idx < 2048; idx += 400) {
        int row = idx >> 7;
        int rem = idx & 127;
        int col = rem >> 3;
        int c4  = rem & 7;
        const float4 v = *reinterpret_cast<const float4*>(
            vol + ((size_t)((b * H_ + oy0 + row) * W_ + ox0 + col)) * C_ + 4 * c4);
        *reinterpret_cast<float4*>(&patch[(row * 16 + col) * PCOL + 4 * c4]) = v;
    }
    __syncthreads();

    const int tm = tid % 25;   // ch quad: ch0 = 4*tm
    const int tn = tid / 25;   // px quad: px = 4*tn + {0..3}

    // my 4 pixels
    int pxl[4], pyl[4];
#pragma unroll
    for (int jj = 0; jj < 4; ++jj) {
        int p = 4 * tn + jj;
        pyl[jj] = p >> 3;
        pxl[jj] = p & 7;
    }

    u64t acc2[4][4];   // [ch][px], each packed over (c even, c odd) partials
#pragma unroll
    for (int i = 0; i < 4; ++i)
#pragma unroll
        for (int jj = 0; jj < 4; ++jj) acc2[i][jj] = 0ull;

    const float* wbase = g_wpack + 8 * tm;

    for (int k = 0; k < 25; ++k) {
        const int fy2 = (k / 5) * 2, fx2 = (k % 5) * 2;
        const float* pb[4];
#pragma unroll
        for (int jj = 0; jj < 4; ++jj)
            pb[jj] = &patch[((pyl[jj] + fy2) * 16 + pxl[jj] + fx2) * PCOL];
        const float* wk = wbase + k * 3200;

#pragma unroll 4
        for (int c2 = 0; c2 < 16; ++c2) {
            f4u A0, A1;
            A0.f = __ldg(reinterpret_cast<const float4*>(wk + c2 * 200));
            A1.f = __ldg(reinterpret_cast<const float4*>(wk + c2 * 200 + 4));
            u64t ap[4] = {A0.u.x, A0.u.y, A1.u.x, A1.u.y};
            u64t bp[4];
#pragma unroll
            for (int jj = 0; jj < 4; ++jj)
                bp[jj] = *reinterpret_cast<const u64t*>(pb[jj] + 2 * c2);
#pragma unroll
            for (int i = 0; i < 4; ++i)
#pragma unroll
                for (int jj = 0; jj < 4; ++jj)
                    acc2[i][jj] = ffma2(ap[i], bp[jj], acc2[i][jj]);
        }
    }

    const int ch0 = 4 * tm;
    const float bo0 = __ldg(b_off + ch0),     bo1 = __ldg(b_off + ch0 + 1);
    const float bo2 = __ldg(b_off + ch0 + 2), bo3 = __ldg(b_off + ch0 + 3);
#pragma unroll
    for (int jj = 0; jj < 4; ++jj) {
        int oy = oy0 + pyl[jj], ox = ox0 + pxl[jj];
        float2 e0 = up2(acc2[0][jj]);
        float2 e1 = up2(acc2[1][jj]);
        float2 e2 = up2(acc2[2][jj]);
        float2 e3 = up2(acc2[3][jj]);
        float4 r = make_float4(e0.x + e0.y + bo0, e1.x + e1.y + bo1,
                               e2.x + e2.y + bo2, e3.x + e3.y + bo3);
        *reinterpret_cast<float4*>(
            &g_offbuf[((size_t)((b * OH_ + oy) * OW_ + ox)) * OCH_ + ch0]) = r;
    }
}

// ---------------------------------------------------------------------------
// Kernel B v5: deformable gather + grouped conv.
// Tile 8y x 8x = 64 px, 128 threads. Warp = (out-half oh, px-half ph);
// lane i=lane>>3 owns outs 32*oh+8i..+7, j=lane&7 owns px 32*ph+4j..+3.
// Per c-step: 2 lane-varying LDS.128 weights (1 wf each) + 2 LDS.64 samples
// (1 wf each) -> 4 wf/c (was 6). Offsets via one float4/sample. Single-buffer
// smem (25 KB) + 2 syncs/tap -> 5 blocks/SM.
// ---------------------------------------------------------------------------
#define SS_C   66                  // c-row stride (floats)
#define SS_G2  (32 * SS_C + 8)     // 2120: group stride
#define SS_BUF (2 * SS_G2)         // 4240 floats

__global__ __launch_bounds__(128, 5)
void dcn_kernel(const float* __restrict__ vol,
                const float* __restrict__ w_dcn,
                const float* __restrict__ b_dcn,
                float* __restrict__ out)
{
    __shared__ __align__(16) float Ss[SS_BUF];   // 17.0 KB
    __shared__ __align__(16) float wks[2048];    // 8.2 KB

    const int tid  = threadIdx.x;
    const int lane = tid & 31;
    const int warp = tid >> 5;
    const int ox0 = blockIdx.x * 8;
    const int oy0 = blockIdx.y * 8;
    const int b   = blockIdx.z;

    // GEMM roles
    const int oh = warp & 1;          // out half (== deform group)
    const int ph = warp >> 1;         // px half
    const int oi = lane >> 3;         // out oct: outs 32*oh + 8*oi .. +7
    const int pj = lane & 7;          // px quad: px 32*ph + 4*pj .. +3
    const int o0 = 32 * oh + 8 * oi;

    // Gather roles: per pass, 4 samples x 8 lanes
    const int q = lane >> 3;
    const int j = lane & 7;
    const int sBase = warp * 32;

    const float* volb = vol + (size_t)b * (H_ * W_ * C_);
    const float* offb = g_offbuf + ((size_t)(b * OH_ + oy0) * OW_ + ox0) * OCH_;

    u64t acc2[4][4];   // [out-pair][px]
#pragma unroll
    for (int t = 0; t < 4; ++t)
#pragma unroll
        for (int jj = 0; jj < 4; ++jj) acc2[t][jj] = 0ull;

    for (int k = 0; k < 25; ++k) {
        __syncthreads();   // previous tap's GEMM reads complete

        // Stage this tap's weights (coalesced float4, conflict-free)
        {
            const float4* wsrc = reinterpret_cast<const float4*>(w_dcn + k * 2048);
            float4* wdst = reinterpret_cast<float4*>(wks);
#pragma unroll
            for (int i = 0; i < 4; ++i)
                wdst[tid + i * 128] = wsrc[tid + i * 128];
        }

        const int fy = k / 5, fx = k - fy * 5;
        const float dky = (float)((fy - 2) * 2);
        const float dkx = (float)((fx - 2) * 2);

        // Gather 128 samples (warp-cooperative, full-line LDG.128)
#pragma unroll
        for (int pass = 0; pass < 8; ++pass) {
            int s = sBase + pass * 4 + q;
            int p = s & 63, g = s >> 6;
            int pyi = p >> 3, pxi = p & 7;

            // one float4 = {dy_g0, dy_g1, dx_g0, dx_g1} for this (px, k)
            float4 ov = __ldg(reinterpret_cast<const float4*>(
                offb + (pyi * OW_ + pxi) * OCH_ + k * 4));
            float offy = g ? ov.y : ov.x;
            float offx = g ? ov.w : ov.z;

            float py = (float)(oy0 + pyi + 4) + dky + offy;
            float px = (float)(ox0 + pxi + 4) + dkx + offx;
            py = fminf(fmaxf(py, 0.0f), 127.0f);
            px = fminf(fmaxf(px, 0.0f), 127.0f);
            float y0f = fminf(floorf(py), 126.0f);
            float x0f = fminf(floorf(px), 126.0f);
            float wy = py - y0f, wx = px - x0f;
            int y0 = (int)y0f, x0 = (int)x0f;

            const float4* r0 = reinterpret_cast<const float4*>(
                volb + ((size_t)(y0 * W_ + x0)) * C_);
            f4u L0, L1, L2, L3;
            L0.f = r0[j];
            L1.f = r0[j + 8];
            L2.f = r0[j + 1024];
            L3.f = r0[j + 1032];

            u64t c00p = dup2((1.0f - wy) * (1.0f - wx));
            u64t c01p = dup2((1.0f - wy) * wx);
            u64t c10p = dup2(wy * (1.0f - wx));
            u64t c11p = dup2(wy * wx);

            ulonglong2 svu;
            svu.x = ffma2(L0.u.x, c00p, ffma2(L1.u.x, c01p,
                        ffma2(L2.u.x, c10p, fmul2(L3.u.x, c11p))));
            svu.y = ffma2(L0.u.y, c00p, ffma2(L1.u.y, c01p,
                        ffma2(L2.u.y, c10p, fmul2(L3.u.y, c11p))));
            float2 s01 = up2(svu.x);
            float2 s23 = up2(svu.y);

            float* dstb = &Ss[g * SS_G2 + p];
            dstb[(4 * j    ) * SS_C] = s01.x;
            dstb[(4 * j + 1) * SS_C] = s01.y;
            dstb[(4 * j + 2) * SS_C] = s23.x;
            dstb[(4 * j + 3) * SS_C] = s23.y;
        }
        __syncthreads();

        // GEMM over C=32: lane-varying LDS.128 weights + LDS.64 sample pairs
        const float* Sg = Ss + oh * SS_G2 + 32 * ph + 4 * pj;
        const float* wo = wks + o0;
#pragma unroll 8
        for (int c = 0; c < 32; ++c) {
            f4u W0, W1;
            W0.f = *reinterpret_cast<const float4*>(wo + c * 64);
            W1.f = *reinterpret_cast<const float4*>(wo + c * 64 + 4);
            u64t wp[4] = {W0.u.x, W0.u.y, W1.u.x, W1.u.y};
            float2 sa = *reinterpret_cast<const float2*>(Sg + c * SS_C);
            float2 sb = *reinterpret_cast<const float2*>(Sg + c * SS_C + 2);
            u64t b0 = dup2(sa.x);
            u64t b1 = dup2(sa.y);
            u64t b2 = dup2(sb.x);
            u64t b3 = dup2(sb.y);
#pragma unroll
            for (int t = 0; t < 4; ++t) {
                acc2[t][0] = ffma2(wp[t], b0, acc2[t][0]);
                acc2[t][1] = ffma2(wp[t], b1, acc2[t][1]);
                acc2[t][2] = ffma2(wp[t], b2, acc2[t][2]);
                acc2[t][3] = ffma2(wp[t], b3, acc2[t][3]);
            }
        }
    }

    // Epilogue: bias + stores. Thread writes 8 outs x 4 px.
    f4u B0, B1;
    B0.f = __ldg(reinterpret_cast<const float4*>(b_dcn + o0));
    B1.f = __ldg(reinterpret_cast<const float4*>(b_dcn + o0 + 4));
    float bo[8];
    {
        float2 t0 = up2(B0.u.x), t1 = up2(B0.u.y), t2 = up2(B1.u.x), t3 = up2(B1.u.y);
        bo[0]=t0.x; bo[1]=t0.y; bo[2]=t1.x; bo[3]=t1.y;
        bo[4]=t2.x; bo[5]=t2.y; bo[6]=t3.x; bo[7]=t3.y;
    }
#pragma unroll
    for (int jj = 0; jj < 4; ++jj) {
        int p  = 32 * ph + 4 * pj + jj;
        int oy = oy0 + (p >> 3), ox = ox0 + (p & 7);
        float* opx = out + ((size_t)((b * OH_ + oy) * OW_ + ox)) * F_ + o0;
        float2 p0 = up2(acc2[0][jj]);
        float2 p1 = up2(acc2[1][jj]);
        float2 p2 = up2(acc2[2][jj]);
        float2 p3 = up2(acc2[3][jj]);
        float4 r0 = make_float4(p0.x + bo[0], p0.y + bo[1], p1.x + bo[2], p1.y + bo[3]);
        float4 r1 = make_float4(p2.x + bo[4], p2.y + bo[5], p3.x + bo[6], p3.y + bo[7]);
        *reinterpret_cast<float4*>(opx)     = r0;
        *reinterpret_cast<float4*>(opx + 4) = r1;
    }
}

// ---------------------------------------------------------------------------
extern "C" void kernel_launch(void* const* d_in, const int* in_sizes, int n_in,
                              void* d_out, int out_size)
{
    const float* vol   = (const float*)d_in[0];
    const float* w_off = (const float*)d_in[1];
    const float* b_off = (const float*)d_in[2];
    const float* w_dcn = (const float*)d_in[3];
    const float* b_dcn = (const float*)d_in[4];
    float* out = (float*)d_out;

    pack_woff_kernel<<<(25 * 16 * 100 * 2 + 255) / 256, 256>>>(w_off);

    dim3 gA(OW_ / 8, OH_ / 8, B_);   // (15, 15, 4)
    offset_conv_kernel<<<gA, 400>>>(vol, b_off);

    dim3 gB(OW_ / 8, OH_ / 8, B_);   // (15, 15, 4)
    dcn_kernel<<<gB, 128>>>(vol, w_dcn, b_dcn, out);
}

// round 7
// speedup vs baseline: 1.2680x; 1.2680x over previous
#include <cuda_runtime.h>

// Problem constants
#define H_   128
#define W_   128
#define C_   32
#define B_   4
#define OH_  120
#define OW_  120
#define OCH_ 100
#define F_   64

__device__ float g_offbuf[(size_t)B_ * OH_ * OW_ * OCH_];

// ---- packed f32x2 helpers (sm_103a FFMA2 path) ----------------------------
typedef unsigned long long u64t;

__device__ __forceinline__ u64t ffma2(u64t a, u64t b, u64t c) {
    u64t d;
    asm("fma.rn.f32x2 %0, %1, %2, %3;" : "=l"(d) : "l"(a), "l"(b), "l"(c));
    return d;
}
__device__ __forceinline__ u64t fmul2(u64t a, u64t b) {
    u64t d;
    asm("mul.rn.f32x2 %0, %1, %2;" : "=l"(d) : "l"(a), "l"(b));
    return d;
}
__device__ __forceinline__ u64t dup2(float x) {
    u64t d; unsigned xi = __float_as_uint(x);
    asm("mov.b64 %0, {%1, %1};" : "=l"(d) : "r"(xi));
    return d;
}
__device__ __forceinline__ float2 up2(u64t v) {
    float2 f;
    asm("mov.b64 {%0, %1}, %2;" : "=f"(f.x), "=f"(f.y) : "l"(v));
    return f;
}
union f4u { float4 f; ulonglong2 u; };

// ---------------------------------------------------------------------------
// Kernel A: dense dilated 5x5 conv -> 100 offset channels. (R4/R5 version,
// measured ~210us.) Tile 8x8 px, 200 threads, thread tile 4ch x 8px, patch in
// smem stride-36, weights via single __ldg float4 per c-step (broadcast-
// local), one __syncthreads total.
// ---------------------------------------------------------------------------
#define PCOL 36
__global__ __launch_bounds__(200, 3)
void offset_conv_kernel(const float* __restrict__ vol,
                        const float* __restrict__ w_off,
                        const float* __restrict__ b_off)
{
    __shared__ float patch[16 * 16 * PCOL];  // 36 KB

    const int tid = threadIdx.x;
    const int ox0 = blockIdx.x * 8;
    const int oy0 = blockIdx.y * 8;
    const int b   = blockIdx.z;

    for (int idx = tid; idx < 2048; idx += 200) {
        int row = idx >> 7;
        int rem = idx & 127;
        int col = rem >> 3;
        int c4  = rem & 7;
        const float4 v = *reinterpret_cast<const float4*>(
            vol + ((size_t)((b * H_ + oy0 + row) * W_ + ox0 + col)) * C_ + 4 * c4);
        *reinterpret_cast<float4*>(&patch[(row * 16 + col) * PCOL + 4 * c4]) = v;
    }
    __syncthreads();

    const int tm = tid % 25;
    const int tn = tid / 25;

    u64t acc2[2][8];
#pragma unroll
    for (int i = 0; i < 2; ++i)
#pragma unroll
        for (int jj = 0; jj < 8; ++jj) acc2[i][jj] = 0ull;

    const float* wbase = w_off + 4 * tm;

    for (int k = 0; k < 25; ++k) {
        const int fy2 = (k / 5) * 2, fx2 = (k % 5) * 2;
        const float* pb = &patch[(fy2 * 16 + tn + fx2) * PCOL];
        const float* wk = wbase + k * 3200;
#pragma unroll 8
        for (int c = 0; c < 32; ++c) {
            f4u Av; Av.f = __ldg(reinterpret_cast<const float4*>(wk + c * 100));
            u64t ap[2] = {Av.u.x, Av.u.y};
            u64t bp[8];
#pragma unroll
            for (int jj = 0; jj < 8; ++jj) bp[jj] = dup2(pb[jj * (16 * PCOL) + c]);
#pragma unroll
            for (int i = 0; i < 2; ++i)
#pragma unroll
                for (int jj = 0; jj < 8; ++jj)
                    acc2[i][jj] = ffma2(ap[i], bp[jj], acc2[i][jj]);
        }
    }

    const int ch0 = 4 * tm;
    const float bo0 = __ldg(b_off + ch0),     bo1 = __ldg(b_off + ch0 + 1);
    const float bo2 = __ldg(b_off + ch0 + 2), bo3 = __ldg(b_off + ch0 + 3);
#pragma unroll
    for (int jj = 0; jj < 8; ++jj) {
        int oy = oy0 + jj, ox = ox0 + tn;
        float2 lo = up2(acc2[0][jj]);
        float2 hi = up2(acc2[1][jj]);
        float4 r = make_float4(lo.x + bo0, lo.y + bo1, hi.x + bo2, hi.y + bo3);
        *reinterpret_cast<float4*>(
            &g_offbuf[((size_t)((b * OH_ + oy) * OW_ + ox)) * OCH_ + ch0]) = r;
    }
}

// ---------------------------------------------------------------------------
// Kernel B v5: deformable gather + grouped conv. (R6 dcn, isolated measure.)
// Tile 8y x 8x = 64 px, 128 threads. Warp = (out-half oh, px-half ph);
// lane i=lane>>3 owns outs 32*oh+8i..+7, j=lane&7 owns px 32*ph+4j..+3.
// Per c-step: 2 lane-varying LDS.128 weights + 2 LDS.64 samples -> ~4 wf/c.
// Offsets via one float4/sample. Single-buffer smem (25 KB), 2 syncs/tap,
// 5 blocks/SM.
// ---------------------------------------------------------------------------
#define SS_C   66                  // c-row stride (floats)
#define SS_G2  (32 * SS_C + 8)     // 2120: group stride
#define SS_BUF (2 * SS_G2)         // 4240 floats

__global__ __launch_bounds__(128, 5)
void dcn_kernel(const float* __restrict__ vol,
                const float* __restrict__ w_dcn,
                const float* __restrict__ b_dcn,
                float* __restrict__ out)
{
    __shared__ __align__(16) float Ss[SS_BUF];   // 17.0 KB
    __shared__ __align__(16) float wks[2048];    // 8.2 KB

    const int tid  = threadIdx.x;
    const int lane = tid & 31;
    const int warp = tid >> 5;
    const int ox0 = blockIdx.x * 8;
    const int oy0 = blockIdx.y * 8;
    const int b   = blockIdx.z;

    // GEMM roles
    const int oh = warp & 1;          // out half (== deform group)
    const int ph = warp >> 1;         // px half
    const int oi = lane >> 3;         // out oct: outs 32*oh + 8*oi .. +7
    const int pj = lane & 7;          // px quad: px 32*ph + 4*pj .. +3
    const int o0 = 32 * oh + 8 * oi;

    // Gather roles: per pass, 4 samples x 8 lanes
    const int q = lane >> 3;
    const int j = lane & 7;
    const int sBase = warp * 32;

    const float* volb = vol + (size_t)b * (H_ * W_ * C_);
    const float* offb = g_offbuf + ((size_t)(b * OH_ + oy0) * OW_ + ox0) * OCH_;

    u64t acc2[4][4];   // [out-pair][px]
#pragma unroll
    for (int t = 0; t < 4; ++t)
#pragma unroll
        for (int jj = 0; jj < 4; ++jj) acc2[t][jj] = 0ull;

    for (int k = 0; k < 25; ++k) {
        __syncthreads();   // previous tap's GEMM reads complete

        // Stage this tap's weights (coalesced float4, conflict-free)
        {
            const float4* wsrc = reinterpret_cast<const float4*>(w_dcn + k * 2048);
            float4* wdst = reinterpret_cast<float4*>(wks);
#pragma unroll
            for (int i = 0; i < 4; ++i)
                wdst[tid + i * 128] = wsrc[tid + i * 128];
        }

        const int fy = k / 5, fx = k - fy * 5;
        const float dky = (float)((fy - 2) * 2);
        const float dkx = (float)((fx - 2) * 2);

        // Gather 128 samples (warp-cooperative, full-line LDG.128)
#pragma unroll
        for (int pass = 0; pass < 8; ++pass) {
            int s = sBase + pass * 4 + q;
            int p = s & 63, g = s >> 6;
            int pyi = p >> 3, pxi = p & 7;

            // one float4 = {dy_g0, dy_g1, dx_g0, dx_g1} for this (px, k)
            float4 ov = __ldg(reinterpret_cast<const float4*>(
                offb + (pyi * OW_ + pxi) * OCH_ + k * 4));
            float offy = g ? ov.y : ov.x;
            float offx = g ? ov.w : ov.z;

            float py = (float)(oy0 + pyi + 4) + dky + offy;
            float px = (float)(ox0 + pxi + 4) + dkx + offx;
            py = fminf(fmaxf(py, 0.0f), 127.0f);
            px = fminf(fmaxf(px, 0.0f), 127.0f);
            float y0f = fminf(floorf(py), 126.0f);
            float x0f = fminf(floorf(px), 126.0f);
            float wy = py - y0f, wx = px - x0f;
            int y0 = (int)y0f, x0 = (int)x0f;

            const float4* r0 = reinterpret_cast<const float4*>(
                volb + ((size_t)(y0 * W_ + x0)) * C_);
            f4u L0, L1, L2, L3;
            L0.f = r0[j];
            L1.f = r0[j + 8];
            L2.f = r0[j + 1024];
            L3.f = r0[j + 1032];

            u64t c00p = dup2((1.0f - wy) * (1.0f - wx));
            u64t c01p = dup2((1.0f - wy) * wx);
            u64t c10p = dup2(wy * (1.0f - wx));
            u64t c11p = dup2(wy * wx);

            ulonglong2 svu;
            svu.x = ffma2(L0.u.x, c00p, ffma2(L1.u.x, c01p,
                        ffma2(L2.u.x, c10p, fmul2(L3.u.x, c11p))));
            svu.y = ffma2(L0.u.y, c00p, ffma2(L1.u.y, c01p,
                        ffma2(L2.u.y, c10p, fmul2(L3.u.y, c11p))));
            float2 s01 = up2(svu.x);
            float2 s23 = up2(svu.y);

            float* dstb = &Ss[g * SS_G2 + p];
            dstb[(4 * j    ) * SS_C] = s01.x;
            dstb[(4 * j + 1) * SS_C] = s01.y;
            dstb[(4 * j + 2) * SS_C] = s23.x;
            dstb[(4 * j + 3) * SS_C] = s23.y;
        }
        __syncthreads();

        // GEMM over C=32: lane-varying LDS.128 weights + LDS.64 sample pairs
        const float* Sg = Ss + oh * SS_G2 + 32 * ph + 4 * pj;
        const float* wo = wks + o0;
#pragma unroll 8
        for (int c = 0; c < 32; ++c) {
            f4u W0, W1;
            W0.f = *reinterpret_cast<const float4*>(wo + c * 64);
            W1.f = *reinterpret_cast<const float4*>(wo + c * 64 + 4);
            u64t wp[4] = {W0.u.x, W0.u.y, W1.u.x, W1.u.y};
            float2 sa = *reinterpret_cast<const float2*>(Sg + c * SS_C);
            float2 sb = *reinterpret_cast<const float2*>(Sg + c * SS_C + 2);
            u64t b0 = dup2(sa.x);
            u64t b1 = dup2(sa.y);
            u64t b2 = dup2(sb.x);
            u64t b3 = dup2(sb.y);
#pragma unroll
            for (int t = 0; t < 4; ++t) {
                acc2[t][0] = ffma2(wp[t], b0, acc2[t][0]);
                acc2[t][1] = ffma2(wp[t], b1, acc2[t][1]);
                acc2[t][2] = ffma2(wp[t], b2, acc2[t][2]);
                acc2[t][3] = ffma2(wp[t], b3, acc2[t][3]);
            }
        }
    }

    // Epilogue: bias + stores. Thread writes 8 outs x 4 px.
    f4u B0, B1;
    B0.f = __ldg(reinterpret_cast<const float4*>(b_dcn + o0));
    B1.f = __ldg(reinterpret_cast<const float4*>(b_dcn + o0 + 4));
    float bo[8];
    {
        float2 t0 = up2(B0.u.x), t1 = up2(B0.u.y), t2 = up2(B1.u.x), t3 = up2(B1.u.y);
        bo[0]=t0.x; bo[1]=t0.y; bo[2]=t1.x; bo[3]=t1.y;
        bo[4]=t2.x; bo[5]=t2.y; bo[6]=t3.x; bo[7]=t3.y;
    }
#pragma unroll
    for (int jj = 0; jj < 4; ++jj) {
        int p  = 32 * ph + 4 * pj + jj;
        int oy = oy0 + (p >> 3), ox = ox0 + (p & 7);
        float* opx = out + ((size_t)((b * OH_ + oy) * OW_ + ox)) * F_ + o0;
        float2 p0 = up2(acc2[0][jj]);
        float2 p1 = up2(acc2[1][jj]);
        float2 p2 = up2(acc2[2][jj]);
        float2 p3 = up2(acc2[3][jj]);
        float4 r0 = make_float4(p0.x + bo[0], p0.y + bo[1], p1.x + bo[2], p1.y + bo[3]);
        float4 r1 = make_float4(p2.x + bo[4], p2.y + bo[5], p3.x + bo[6], p3.y + bo[7]);
        *reinterpret_cast<float4*>(opx)     = r0;
        *reinterpret_cast<float4*>(opx + 4) = r1;
    }
}

// ---------------------------------------------------------------------------
extern "C" void kernel_launch(void* const* d_in, const int* in_sizes, int n_in,
                              void* d_out, int out_size)
{
    const float* vol   = (const float*)d_in[0];
    const float* w_off = (const float*)d_in[1];
    const float* b_off = (const float*)d_in[2];
    const float* w_dcn = (const float*)d_in[3];
    const float* b_dcn = (const float*)d_in[4];
    float* out = (float*)d_out;

    dim3 gA(OW_ / 8, OH_ / 8, B_);   // (15, 15, 4)
    offset_conv_kernel<<<gA, 200>>>(vol, w_off, b_off);

    dim3 gB(OW_ / 8, OH_ / 8, B_);   // (15, 15, 4)
    dcn_kernel<<<gB, 128>>>(vol, w_dcn, b_dcn, out);
}

// round 8
// speedup vs baseline: 1.2861x; 1.0142x over previous
#include <cuda_runtime.h>

// Problem constants
#define H_   128
#define W_   128
#define C_   32
#define B_   4
#define OH_  120
#define OW_  120
#define OCH_ 100
#define F_   64

__device__ float g_offbuf[(size_t)B_ * OH_ * OW_ * OCH_];

// ---- packed f32x2 helpers (sm_103a FFMA2 path) ----------------------------
typedef unsigned long long u64t;

__device__ __forceinline__ u64t ffma2(u64t a, u64t b, u64t c) {
    u64t d;
    asm("fma.rn.f32x2 %0, %1, %2, %3;" : "=l"(d) : "l"(a), "l"(b), "l"(c));
    return d;
}
__device__ __forceinline__ u64t fmul2(u64t a, u64t b) {
    u64t d;
    asm("mul.rn.f32x2 %0, %1, %2;" : "=l"(d) : "l"(a), "l"(b));
    return d;
}
__device__ __forceinline__ u64t dup2(float x) {
    u64t d; unsigned xi = __float_as_uint(x);
    asm("mov.b64 %0, {%1, %1};" : "=l"(d) : "r"(xi));
    return d;
}
__device__ __forceinline__ float2 up2(u64t v) {
    float2 f;
    asm("mov.b64 {%0, %1}, %2;" : "=f"(f.x), "=f"(f.y) : "l"(v));
    return f;
}
union f4u { float4 f; ulonglong2 u; };

// ---------------------------------------------------------------------------
// Kernel A: dense dilated 5x5 conv -> 100 offset channels. (stable ~218us)
// ---------------------------------------------------------------------------
#define PCOL 36
__global__ __launch_bounds__(200, 3)
void offset_conv_kernel(const float* __restrict__ vol,
                        const float* __restrict__ w_off,
                        const float* __restrict__ b_off)
{
    __shared__ float patch[16 * 16 * PCOL];  // 36 KB

    const int tid = threadIdx.x;
    const int ox0 = blockIdx.x * 8;
    const int oy0 = blockIdx.y * 8;
    const int b   = blockIdx.z;

    for (int idx = tid; idx < 2048; idx += 200) {
        int row = idx >> 7;
        int rem = idx & 127;
        int col = rem >> 3;
        int c4  = rem & 7;
        const float4 v = *reinterpret_cast<const float4*>(
            vol + ((size_t)((b * H_ + oy0 + row) * W_ + ox0 + col)) * C_ + 4 * c4);
        *reinterpret_cast<float4*>(&patch[(row * 16 + col) * PCOL + 4 * c4]) = v;
    }
    __syncthreads();

    const int tm = tid % 25;
    const int tn = tid / 25;

    u64t acc2[2][8];
#pragma unroll
    for (int i = 0; i < 2; ++i)
#pragma unroll
        for (int jj = 0; jj < 8; ++jj) acc2[i][jj] = 0ull;

    const float* wbase = w_off + 4 * tm;

    for (int k = 0; k < 25; ++k) {
        const int fy2 = (k / 5) * 2, fx2 = (k % 5) * 2;
        const float* pb = &patch[(fy2 * 16 + tn + fx2) * PCOL];
        const float* wk = wbase + k * 3200;
#pragma unroll 8
        for (int c = 0; c < 32; ++c) {
            f4u Av; Av.f = __ldg(reinterpret_cast<const float4*>(wk + c * 100));
            u64t ap[2] = {Av.u.x, Av.u.y};
            u64t bp[8];
#pragma unroll
            for (int jj = 0; jj < 8; ++jj) bp[jj] = dup2(pb[jj * (16 * PCOL) + c]);
#pragma unroll
            for (int i = 0; i < 2; ++i)
#pragma unroll
                for (int jj = 0; jj < 8; ++jj)
                    acc2[i][jj] = ffma2(ap[i], bp[jj], acc2[i][jj]);
        }
    }

    const int ch0 = 4 * tm;
    const float bo0 = __ldg(b_off + ch0),     bo1 = __ldg(b_off + ch0 + 1);
    const float bo2 = __ldg(b_off + ch0 + 2), bo3 = __ldg(b_off + ch0 + 3);
#pragma unroll
    for (int jj = 0; jj < 8; ++jj) {
        int oy = oy0 + jj, ox = ox0 + tn;
        float2 lo = up2(acc2[0][jj]);
        float2 hi = up2(acc2[1][jj]);
        float4 r = make_float4(lo.x + bo0, lo.y + bo1, hi.x + bo2, hi.y + bo3);
        *reinterpret_cast<float4*>(
            &g_offbuf[((size_t)((b * OH_ + oy) * OW_ + ox)) * OCH_ + ch0]) = r;
    }
}

// ---------------------------------------------------------------------------
// Kernel B v6: occupancy-first. Tile 4y x 8x = 32 px, 128 threads, grid 1800.
// smem 17 KB, <=64 regs -> 8 blocks/SM (32 warps, 50% occ).
// Gather: 64 samples (32px x 2g), 4 warps x 4 passes, full-line LDG.128.
// GEMM: warp=(out-half, px-half); lane oi=outs 8, pj=px pair. Per c-step:
// 2 lane-varying LDS.128 weights + 1 LDS.64 sample pair + 8 FFMA2.
// ---------------------------------------------------------------------------
#define SS_P2  34                 // c-row stride (32 px + 2 pad, even)
#define SS_Gb  (32 * SS_P2 + 8)   // 1096: group stride
#define SS_SZ  (2 * SS_Gb)        // 2192 floats

__global__ __launch_bounds__(128, 8)
void dcn_kernel(const float* __restrict__ vol,
                const float* __restrict__ w_dcn,
                const float* __restrict__ b_dcn,
                float* __restrict__ out)
{
    __shared__ __align__(16) float Ss[SS_SZ];    // 8.8 KB
    __shared__ __align__(16) float wks[2048];    // 8.2 KB

    const int tid  = threadIdx.x;
    const int lane = tid & 31;
    const int warp = tid >> 5;
    const int ox0 = blockIdx.x * 8;
    const int oy0 = blockIdx.y * 4;
    const int b   = blockIdx.z;

    // GEMM roles: warp = (out-half, px-half)
    const int oh = warp & 1;          // outs 32*oh..+31 (== deform group)
    const int ph = warp >> 1;         // px 16*ph..+15
    const int oi = lane >> 3;         // outs o0..o0+7
    const int pj = lane & 7;          // px pair 16*ph + 2*pj
    const int o0 = 32 * oh + 8 * oi;

    // Gather roles: per pass, 4 samples x 8 lanes; 4 passes
    const int q = lane >> 3;
    const int j = lane & 7;
    const int sBase = warp * 16;

    const float* volb = vol + (size_t)b * (H_ * W_ * C_);
    const float* offb = g_offbuf + ((size_t)(b * OH_ + oy0) * OW_ + ox0) * OCH_;

    u64t acc2[4][2];   // [out-pair][px]
#pragma unroll
    for (int t = 0; t < 4; ++t) {
        acc2[t][0] = 0ull; acc2[t][1] = 0ull;
    }

    for (int k = 0; k < 25; ++k) {
        __syncthreads();   // previous tap's GEMM reads complete

        // Stage this tap's weights (coalesced float4, conflict-free)
        {
            const float4* wsrc = reinterpret_cast<const float4*>(w_dcn + k * 2048);
            float4* wdst = reinterpret_cast<float4*>(wks);
#pragma unroll
            for (int i = 0; i < 4; ++i)
                wdst[tid + i * 128] = wsrc[tid + i * 128];
        }

        const int fy = k / 5, fx = k - fy * 5;
        const float dky = (float)((fy - 2) * 2);
        const float dkx = (float)((fx - 2) * 2);

        // Gather 64 samples (4 passes x 4 warps x 4 samples)
#pragma unroll
        for (int pass = 0; pass < 4; ++pass) {
            int s = sBase + pass * 4 + q;
            int p = s & 31, g = s >> 5;
            int pyi = p >> 3, pxi = p & 7;

            float4 ov = __ldg(reinterpret_cast<const float4*>(
                offb + (pyi * OW_ + pxi) * OCH_ + k * 4));
            float offy = g ? ov.y : ov.x;
            float offx = g ? ov.w : ov.z;

            float py = (float)(oy0 + pyi + 4) + dky + offy;
            float px = (float)(ox0 + pxi + 4) + dkx + offx;
            py = fminf(fmaxf(py, 0.0f), 127.0f);
            px = fminf(fmaxf(px, 0.0f), 127.0f);
            float y0f = fminf(floorf(py), 126.0f);
            float x0f = fminf(floorf(px), 126.0f);
            float wy = py - y0f, wx = px - x0f;
            int y0 = (int)y0f, x0 = (int)x0f;

            const float4* r0 = reinterpret_cast<const float4*>(
                volb + ((size_t)(y0 * W_ + x0)) * C_);
            f4u L0, L1, L2, L3;
            L0.f = r0[j];
            L1.f = r0[j + 8];
            L2.f = r0[j + 1024];
            L3.f = r0[j + 1032];

            u64t c00p = dup2((1.0f - wy) * (1.0f - wx));
            u64t c01p = dup2((1.0f - wy) * wx);
            u64t c10p = dup2(wy * (1.0f - wx));
            u64t c11p = dup2(wy * wx);

            ulonglong2 svu;
            svu.x = ffma2(L0.u.x, c00p, ffma2(L1.u.x, c01p,
                        ffma2(L2.u.x, c10p, fmul2(L3.u.x, c11p))));
            svu.y = ffma2(L0.u.y, c00p, ffma2(L1.u.y, c01p,
                        ffma2(L2.u.y, c10p, fmul2(L3.u.y, c11p))));
            float2 s01 = up2(svu.x);
            float2 s23 = up2(svu.y);

            float* dstb = &Ss[g * SS_Gb + p];
            dstb[(4 * j    ) * SS_P2] = s01.x;
            dstb[(4 * j + 1) * SS_P2] = s01.y;
            dstb[(4 * j + 2) * SS_P2] = s23.x;
            dstb[(4 * j + 3) * SS_P2] = s23.y;
        }
        __syncthreads();

        // GEMM over C=32
        const float* Sg = Ss + oh * SS_Gb + 16 * ph + 2 * pj;
        const float* wo = wks + o0;
#pragma unroll 8
        for (int c = 0; c < 32; ++c) {
            f4u W0, W1;
            W0.f = *reinterpret_cast<const float4*>(wo + c * 64);
            W1.f = *reinterpret_cast<const float4*>(wo + c * 64 + 4);
            u64t wp[4] = {W0.u.x, W0.u.y, W1.u.x, W1.u.y};
            float2 sa = *reinterpret_cast<const float2*>(Sg + c * SS_P2);
            u64t b0 = dup2(sa.x);
            u64t b1 = dup2(sa.y);
#pragma unroll
            for (int t = 0; t < 4; ++t) {
                acc2[t][0] = ffma2(wp[t], b0, acc2[t][0]);
                acc2[t][1] = ffma2(wp[t], b1, acc2[t][1]);
            }
        }
    }

    // Epilogue: bias + stores. Thread writes 8 outs x 2 px.
    f4u B0, B1;
    B0.f = __ldg(reinterpret_cast<const float4*>(b_dcn + o0));
    B1.f = __ldg(reinterpret_cast<const float4*>(b_dcn + o0 + 4));
    float bo[8];
    {
        float2 t0 = up2(B0.u.x), t1 = up2(B0.u.y), t2 = up2(B1.u.x), t3 = up2(B1.u.y);
        bo[0]=t0.x; bo[1]=t0.y; bo[2]=t1.x; bo[3]=t1.y;
        bo[4]=t2.x; bo[5]=t2.y; bo[6]=t3.x; bo[7]=t3.y;
    }
#pragma unroll
    for (int jj = 0; jj < 2; ++jj) {
        int p  = 16 * ph + 2 * pj + jj;
        int oy = oy0 + (p >> 3), ox = ox0 + (p & 7);
        float* opx = out + ((size_t)((b * OH_ + oy) * OW_ + ox)) * F_ + o0;
        float2 p0 = up2(acc2[0][jj]);
        float2 p1 = up2(acc2[1][jj]);
        float2 p2 = up2(acc2[2][jj]);
        float2 p3 = up2(acc2[3][jj]);
        float4 r0 = make_float4(p0.x + bo[0], p0.y + bo[1], p1.x + bo[2], p1.y + bo[3]);
        float4 r1 = make_float4(p2.x + bo[4], p2.y + bo[5], p3.x + bo[6], p3.y + bo[7]);
        *reinterpret_cast<float4*>(opx)     = r0;
        *reinterpret_cast<float4*>(opx + 4) = r1;
    }
}

// ---------------------------------------------------------------------------
extern "C" void kernel_launch(void* const* d_in, const int* in_sizes, int n_in,
                              void* d_out, int out_size)
{
    const float* vol   = (const float*)d_in[0];
    const float* w_off = (const float*)d_in[1];
    const float* b_off = (const float*)d_in[2];
    const float* w_dcn = (const float*)d_in[3];
    const float* b_dcn = (const float*)d_in[4];
    float* out = (float*)d_out;

    dim3 gA(OW_ / 8, OH_ / 8, B_);   // (15, 15, 4)
    offset_conv_kernel<<<gA, 200>>>(vol, w_off, b_off);

    dim3 gB(OW_ / 8, OH_ / 4, B_);   // (15, 30, 4) = 1800 blocks
    dcn_kernel<<<gB, 128>>>(vol, w_dcn, b_dcn, out);
}

// round 9
// speedup vs baseline: 1.3365x; 1.0392x over previous
#include <cuda_runtime.h>

// Problem constants
#define H_   128
#define W_   128
#define C_   32
#define B_   4
#define OH_  120
#define OW_  120
#define OCH_ 100
#define F_   64

__device__ float g_offbuf[(size_t)B_ * OH_ * OW_ * OCH_];

// ---- packed f32x2 helpers (sm_103a FFMA2 path) ----------------------------
typedef unsigned long long u64t;

__device__ __forceinline__ u64t ffma2(u64t a, u64t b, u64t c) {
    u64t d;
    asm("fma.rn.f32x2 %0, %1, %2, %3;" : "=l"(d) : "l"(a), "l"(b), "l"(c));
    return d;
}
__device__ __forceinline__ u64t fmul2(u64t a, u64t b) {
    u64t d;
    asm("mul.rn.f32x2 %0, %1, %2;" : "=l"(d) : "l"(a), "l"(b));
    return d;
}
__device__ __forceinline__ u64t dup2(float x) {
    u64t d; unsigned xi = __float_as_uint(x);
    asm("mov.b64 %0, {%1, %1};" : "=l"(d) : "r"(xi));
    return d;
}
__device__ __forceinline__ float2 up2(u64t v) {
    float2 f;
    asm("mov.b64 {%0, %1}, %2;" : "=f"(f.x), "=f"(f.y) : "l"(v));
    return f;
}
union f4u { float4 f; ulonglong2 u; };

// ---------------------------------------------------------------------------
// Kernel A v7: dense dilated 5x5 conv -> 100 offset channels.
// Tile 8y x 8x = 64 px, 200 threads: tn=tid&7 (pixel row), tm=tid>>3 (ch quad).
// TRANSPOSED patch [row][c][col] (c-stride 20, row-stride 644): the B operand
// is a contiguous pixel-pair -> LDS.64, FFMA2 packs over pixels.
// Per c-step: 1 LDG.128 (weights, broadcast) + 4 dup2 + 4 LDS.64 + 16 FFMA2
// = 25 issues (was 33). One __syncthreads total.
// ---------------------------------------------------------------------------
#define CST 20     // channel stride in patchT (floats)
#define RST 644    // row stride in patchT   (32*20 + 4 pad; mod 32 = 4)

__global__ __launch_bounds__(200, 4)
void offset_conv_kernel(const float* __restrict__ vol,
                        const float* __restrict__ w_off,
                        const float* __restrict__ b_off)
{
    __shared__ float patchT[16 * RST];   // 41.2 KB

    const int tid = threadIdx.x;
    const int ox0 = blockIdx.x * 8;
    const int oy0 = blockIdx.y * 8;
    const int b   = blockIdx.z;

    // Load patch transposed: 16 rows x 16 cols x 32 ch
    for (int idx = tid; idx < 2048; idx += 200) {
        int row = idx >> 7;          // 128 float4 per row (16 col x 8 c4)
        int rem = idx & 127;
        int col = rem >> 3;
        int c4  = rem & 7;
        const float4 v = *reinterpret_cast<const float4*>(
            vol + ((size_t)((b * H_ + oy0 + row) * W_ + ox0 + col)) * C_ + 4 * c4);
        float* dst = &patchT[row * RST + (4 * c4) * CST + col];
        dst[0 * CST] = v.x;
        dst[1 * CST] = v.y;
        dst[2 * CST] = v.z;
        dst[3 * CST] = v.w;
    }
    __syncthreads();

    const int tn = tid & 7;      // pixel row (y)
    const int tm = tid >> 3;     // ch quad: ch0 = 4*tm  (0..24)

    u64t acc2[4][4];             // [ch][px-pair]; .x = px 2jp, .y = px 2jp+1
#pragma unroll
    for (int i = 0; i < 4; ++i)
#pragma unroll
        for (int jp = 0; jp < 4; ++jp) acc2[i][jp] = 0ull;

    const float* wbase = w_off + 4 * tm;

    for (int k = 0; k < 25; ++k) {
        const int fy2 = (k / 5) * 2, fx2 = (k % 5) * 2;
        const float* pb = &patchT[(tn + fy2) * RST + fx2];
        const float* wk = wbase + k * 3200;
#pragma unroll 8
        for (int c = 0; c < 32; ++c) {
            f4u Av; Av.f = __ldg(reinterpret_cast<const float4*>(wk + c * 100));
            u64t a0 = dup2(Av.f.x), a1 = dup2(Av.f.y);
            u64t a2 = dup2(Av.f.z), a3 = dup2(Av.f.w);
            const float* pc = pb + c * CST;
            u64t bp[4];
#pragma unroll
            for (int jp = 0; jp < 4; ++jp)
                bp[jp] = *reinterpret_cast<const u64t*>(pc + 2 * jp);
#pragma unroll
            for (int jp = 0; jp < 4; ++jp) {
                acc2[0][jp] = ffma2(a0, bp[jp], acc2[0][jp]);
                acc2[1][jp] = ffma2(a1, bp[jp], acc2[1][jp]);
                acc2[2][jp] = ffma2(a2, bp[jp], acc2[2][jp]);
                acc2[3][jp] = ffma2(a3, bp[jp], acc2[3][jp]);
            }
        }
    }

    const int ch0 = 4 * tm;
    const float bo0 = __ldg(b_off + ch0),     bo1 = __ldg(b_off + ch0 + 1);
    const float bo2 = __ldg(b_off + ch0 + 2), bo3 = __ldg(b_off + ch0 + 3);
    const int oy = oy0 + tn;
#pragma unroll
    for (int jp = 0; jp < 4; ++jp) {
        float2 e0 = up2(acc2[0][jp]);
        float2 e1 = up2(acc2[1][jp]);
        float2 e2 = up2(acc2[2][jp]);
        float2 e3 = up2(acc2[3][jp]);
        int ox = ox0 + 2 * jp;
        float* o0p = &g_offbuf[((size_t)((b * OH_ + oy) * OW_ + ox)) * OCH_ + ch0];
        *reinterpret_cast<float4*>(o0p) =
            make_float4(e0.x + bo0, e1.x + bo1, e2.x + bo2, e3.x + bo3);
        *reinterpret_cast<float4*>(o0p + OCH_) =
            make_float4(e0.y + bo0, e1.y + bo1, e2.y + bo2, e3.y + bo3);
    }
}

// ---------------------------------------------------------------------------
// Kernel B v6 (unchanged from R8, measured 240us): occupancy-first.
// Tile 4y x 8x = 32 px, 128 threads, grid 1800, smem 17 KB, 64 regs ->
// 8 blocks/SM (32 warps).
// ---------------------------------------------------------------------------
#define SS_P2  34                 // c-row stride (32 px + 2 pad, even)
#define SS_Gb  (32 * SS_P2 + 8)   // 1096: group stride
#define SS_SZ  (2 * SS_Gb)        // 2192 floats

__global__ __launch_bounds__(128, 8)
void dcn_kernel(const float* __restrict__ vol,
                const float* __restrict__ w_dcn,
                const float* __restrict__ b_dcn,
                float* __restrict__ out)
{
    __shared__ __align__(16) float Ss[SS_SZ];    // 8.8 KB
    __shared__ __align__(16) float wks[2048];    // 8.2 KB

    const int tid  = threadIdx.x;
    const int lane = tid & 31;
    const int warp = tid >> 5;
    const int ox0 = blockIdx.x * 8;
    const int oy0 = blockIdx.y * 4;
    const int b   = blockIdx.z;

    const int oh = warp & 1;
    const int ph = warp >> 1;
    const int oi = lane >> 3;
    const int pj = lane & 7;
    const int o0 = 32 * oh + 8 * oi;

    const int q = lane >> 3;
    const int j = lane & 7;
    const int sBase = warp * 16;

    const float* volb = vol + (size_t)b * (H_ * W_ * C_);
    const float* offb = g_offbuf + ((size_t)(b * OH_ + oy0) * OW_ + ox0) * OCH_;

    u64t acc2[4][2];
#pragma unroll
    for (int t = 0; t < 4; ++t) {
        acc2[t][0] = 0ull; acc2[t][1] = 0ull;
    }

    for (int k = 0; k < 25; ++k) {
        __syncthreads();

        {
            const float4* wsrc = reinterpret_cast<const float4*>(w_dcn + k * 2048);
            float4* wdst = reinterpret_cast<float4*>(wks);
#pragma unroll
            for (int i = 0; i < 4; ++i)
                wdst[tid + i * 128] = wsrc[tid + i * 128];
        }

        const int fy = k / 5, fx = k - fy * 5;
        const float dky = (float)((fy - 2) * 2);
        const float dkx = (float)((fx - 2) * 2);

#pragma unroll
        for (int pass = 0; pass < 4; ++pass) {
            int s = sBase + pass * 4 + q;
            int p = s & 31, g = s >> 5;
            int pyi = p >> 3, pxi = p & 7;

            float4 ov = __ldg(reinterpret_cast<const float4*>(
                offb + (pyi * OW_ + pxi) * OCH_ + k * 4));
            float offy = g ? ov.y : ov.x;
            float offx = g ? ov.w : ov.z;

            float py = (float)(oy0 + pyi + 4) + dky + offy;
            float px = (float)(ox0 + pxi + 4) + dkx + offx;
            py = fminf(fmaxf(py, 0.0f), 127.0f);
            px = fminf(fmaxf(px, 0.0f), 127.0f);
            float y0f = fminf(floorf(py), 126.0f);
            float x0f = fminf(floorf(px), 126.0f);
            float wy = py - y0f, wx = px - x0f;
            int y0 = (int)y0f, x0 = (int)x0f;

            const float4* r0 = reinterpret_cast<const float4*>(
                volb + ((size_t)(y0 * W_ + x0)) * C_);
            f4u L0, L1, L2, L3;
            L0.f = r0[j];
            L1.f = r0[j + 8];
            L2.f = r0[j + 1024];
            L3.f = r0[j + 1032];

            u64t c00p = dup2((1.0f - wy) * (1.0f - wx));
            u64t c01p = dup2((1.0f - wy) * wx);
            u64t c10p = dup2(wy * (1.0f - wx));
            u64t c11p = dup2(wy * wx);

            ulonglong2 svu;
            svu.x = ffma2(L0.u.x, c00p, ffma2(L1.u.x, c01p,
                        ffma2(L2.u.x, c10p, fmul2(L3.u.x, c11p))));
            svu.y = ffma2(L0.u.y, c00p, ffma2(L1.u.y, c01p,
                        ffma2(L2.u.y, c10p, fmul2(L3.u.y, c11p))));
            float2 s01 = up2(svu.x);
            float2 s23 = up2(svu.y);

            float* dstb = &Ss[g * SS_Gb + p];
            dstb[(4 * j    ) * SS_P2] = s01.x;
            dstb[(4 * j + 1) * SS_P2] = s01.y;
            dstb[(4 * j + 2) * SS_P2] = s23.x;
            dstb[(4 * j + 3) * SS_P2] = s23.y;
        }
        __syncthreads();

        const float* Sg = Ss + oh * SS_Gb + 16 * ph + 2 * pj;
        const float* wo = wks + o0;
#pragma unroll 8
        for (int c = 0; c < 32; ++c) {
            f4u W0, W1;
            W0.f = *reinterpret_cast<const float4*>(wo + c * 64);
            W1.f = *reinterpret_cast<const float4*>(wo + c * 64 + 4);
            u64t wp[4] = {W0.u.x, W0.u.y, W1.u.x, W1.u.y};
            float2 sa = *reinterpret_cast<const float2*>(Sg + c * SS_P2);
            u64t b0 = dup2(sa.x);
            u64t b1 = dup2(sa.y);
#pragma unroll
            for (int t = 0; t < 4; ++t) {
                acc2[t][0] = ffma2(wp[t], b0, acc2[t][0]);
                acc2[t][1] = ffma2(wp[t], b1, acc2[t][1]);
            }
        }
    }

    f4u B0, B1;
    B0.f = __ldg(reinterpret_cast<const float4*>(b_dcn + o0));
    B1.f = __ldg(reinterpret_cast<const float4*>(b_dcn + o0 + 4));
    float bo[8];
    {
        float2 t0 = up2(B0.u.x), t1 = up2(B0.u.y), t2 = up2(B1.u.x), t3 = up2(B1.u.y);
        bo[0]=t0.x; bo[1]=t0.y; bo[2]=t1.x; bo[3]=t1.y;
        bo[4]=t2.x; bo[5]=t2.y; bo[6]=t3.x; bo[7]=t3.y;
    }
#pragma unroll
    for (int jj = 0; jj < 2; ++jj) {
        int p  = 16 * ph + 2 * pj + jj;
        int oy = oy0 + (p >> 3), ox = ox0 + (p & 7);
        float* opx = out + ((size_t)((b * OH_ + oy) * OW_ + ox)) * F_ + o0;
        float2 p0 = up2(acc2[0][jj]);
        float2 p1 = up2(acc2[1][jj]);
        float2 p2 = up2(acc2[2][jj]);
        float2 p3 = up2(acc2[3][jj]);
        float4 r0 = make_float4(p0.x + bo[0], p0.y + bo[1], p1.x + bo[2], p1.y + bo[3]);
        float4 r1 = make_float4(p2.x + bo[4], p2.y + bo[5], p3.x + bo[6], p3.y + bo[7]);
        *reinterpret_cast<float4*>(opx)     = r0;
        *reinterpret_cast<float4*>(opx + 4) = r1;
    }
}

// ---------------------------------------------------------------------------
extern "C" void kernel_launch(void* const* d_in, const int* in_sizes, int n_in,
                              void* d_out, int out_size)
{
    const float* vol   = (const float*)d_in[0];
    const float* w_off = (const float*)d_in[1];
    const float* b_off = (const float*)d_in[2];
    const float* w_dcn = (const float*)d_in[3];
    const float* b_dcn = (const float*)d_in[4];
    float* out = (float*)d_out;

    dim3 gA(OW_ / 8, OH_ / 8, B_);   // (15, 15, 4)
    offset_conv_kernel<<<gA, 200>>>(vol, w_off, b_off);

    dim3 gB(OW_ / 8, OH_ / 4, B_);   // (15, 30, 4) = 1800 blocks
    dcn_kernel<<<gB, 128>>>(vol, w_dcn, b_dcn, out);
}

// round 10
// speedup vs baseline: 2.0013x; 1.4974x over previous
#include <cuda_runtime.h>

// Problem constants
#define H_   128
#define W_   128
#define C_   32
#define B_   4
#define OH_  120
#define OW_  120
#define OCH_ 100
#define F_   64

__device__ float g_offbuf[(size_t)B_ * OH_ * OW_ * OCH_];
// tf32-rounded, fragment-ordered offset-conv weights:
// [k][s][t][lane][r]  (25 x 4 x 13 x 32 x 2 uints = 83200)
__device__ unsigned g_bpack[25 * 4 * 13 * 32 * 2];

// ---- packed f32x2 helpers (sm_103a FFMA2 path) ----------------------------
typedef unsigned long long u64t;

__device__ __forceinline__ u64t ffma2(u64t a, u64t b, u64t c) {
    u64t d;
    asm("fma.rn.f32x2 %0, %1, %2, %3;" : "=l"(d) : "l"(a), "l"(b), "l"(c));
    return d;
}
__device__ __forceinline__ u64t fmul2(u64t a, u64t b) {
    u64t d;
    asm("mul.rn.f32x2 %0, %1, %2;" : "=l"(d) : "l"(a), "l"(b));
    return d;
}
__device__ __forceinline__ u64t dup2(float x) {
    u64t d; unsigned xi = __float_as_uint(x);
    asm("mov.b64 %0, {%1, %1};" : "=l"(d) : "r"(xi));
    return d;
}
__device__ __forceinline__ float2 up2(u64t v) {
    float2 f;
    asm("mov.b64 {%0, %1}, %2;" : "=f"(f.x), "=f"(f.y) : "l"(v));
    return f;
}
union f4u { float4 f; ulonglong2 u; };

__device__ __forceinline__ unsigned f2tf32(float x) {
    unsigned r;
    asm("cvt.rna.tf32.f32 %0, %1;" : "=r"(r) : "f"(x));
    return r;
}

// ---------------------------------------------------------------------------
// Prepass: pack w_off (25,32,100) into mma B-fragment order, tf32-rounded.
// b0 = W[k][c=8s+tig][ch=8t+g], b1 = W[k][c=8s+tig+4][ch=8t+g]; ch>=100 -> 0.
// ---------------------------------------------------------------------------
__global__ void pack_woff_kernel(const float* __restrict__ w_off)
{
    int idx = blockIdx.x * 256 + threadIdx.x;
    if (idx >= 25 * 4 * 13 * 32 * 2) return;
    int r    = idx & 1;
    int lane = (idx >> 1) & 31;
    int rem  = idx >> 6;
    int t    = rem % 13;
    int s    = (rem / 13) % 4;
    int k    = rem / (13 * 4);
    int tig  = lane & 3;
    int g    = lane >> 2;
    int c    = 8 * s + tig + 4 * r;
    int ch   = 8 * t + g;
    float v  = (ch < 100) ? w_off[k * 3200 + c * 100 + ch] : 0.0f;
    g_bpack[idx] = f2tf32(v);
}

// ---------------------------------------------------------------------------
// Kernel A v8: offset conv via tf32 mma.sync.m16n8k8.
// Block: 64 px (8y x 8x), 128 threads = 4 warps; warp w owns pixel rows
// {2w, 2w+1} (M-tile of 16 px). N = 104 ch (13 n-tiles), K = 800.
// Patch smem [py][px][c] with pixel stride 36 -> A-frag LDS.32 conflict-free.
// B-frags from g_bpack (LDG.64 contiguous, L1-resident).
// ---------------------------------------------------------------------------
#define PXS 36   // pixel stride in patch (floats)

__global__ __launch_bounds__(128, 5)
void offset_conv_kernel(const float* __restrict__ vol,
                        const float* __restrict__ b_off)
{
    __shared__ float patch[16 * 16 * PXS];   // 36.9 KB

    const int tid  = threadIdx.x;
    const int lane = tid & 31;
    const int warp = tid >> 5;
    const int ox0 = blockIdx.x * 8;
    const int oy0 = blockIdx.y * 8;
    const int b   = blockIdx.z;

    // Load patch: 16x16 px, 32 ch; [P][c] with P-stride 36 (16B-aligned stores)
    for (int idx = tid; idx < 2048; idx += 128) {
        int row = idx >> 7;
        int rem = idx & 127;
        int col = rem >> 3;
        int c4  = rem & 7;
        const float4 v = *reinterpret_cast<const float4*>(
            vol + ((size_t)((b * H_ + oy0 + row) * W_ + ox0 + col)) * C_ + 4 * c4);
        *reinterpret_cast<float4*>(&patch[(row * 16 + col) * PXS + 4 * c4]) = v;
    }
    __syncthreads();

    const int g   = lane >> 2;   // 0..7
    const int tig = lane & 3;    // 0..3

    float cacc[13][4];
#pragma unroll
    for (int t = 0; t < 13; ++t)
#pragma unroll
        for (int i = 0; i < 4; ++i) cacc[t][i] = 0.0f;

    const unsigned* bp = g_bpack + 2 * lane;

#pragma unroll 1
    for (int k = 0; k < 25; ++k) {
        const int fy2 = (k / 5) * 2, fx2 = (k % 5) * 2;
        // A rows: row g -> pixel (y=2w, x=g); row g+8 -> (y=2w+1, x=g)
        const float* pa0 = &patch[((2 * warp + fy2) * 16 + fx2 + g) * PXS];
        const float* pa1 = pa0 + 16 * PXS;

#pragma unroll
        for (int s = 0; s < 4; ++s) {
            unsigned a0 = f2tf32(pa0[8 * s + tig]);
            unsigned a1 = f2tf32(pa1[8 * s + tig]);
            unsigned a2 = f2tf32(pa0[8 * s + tig + 4]);
            unsigned a3 = f2tf32(pa1[8 * s + tig + 4]);
            const uint2* bks = reinterpret_cast<const uint2*>(
                bp + ((k * 4 + s) * 13) * 64);
#pragma unroll
            for (int t = 0; t < 13; ++t) {
                uint2 bb = __ldg(bks + t * 32);
                asm volatile(
                    "mma.sync.aligned.m16n8k8.row.col.f32.tf32.tf32.f32 "
                    "{%0,%1,%2,%3}, {%4,%5,%6,%7}, {%8,%9}, {%0,%1,%2,%3};"
                    : "+f"(cacc[t][0]), "+f"(cacc[t][1]),
                      "+f"(cacc[t][2]), "+f"(cacc[t][3])
                    : "r"(a0), "r"(a1), "r"(a2), "r"(a3),
                      "r"(bb.x), "r"(bb.y));
            }
        }
    }

    // Epilogue: C[row][col]: c0/c1 -> pixel (2w, g) ch {8t+2tig, +1};
    //           c2/c3 -> pixel (2w+1, g).
    const int oyA = oy0 + 2 * warp;
    const int oxA = ox0 + g;
    float* outA = &g_offbuf[((size_t)((b * OH_ + oyA) * OW_ + oxA)) * OCH_];
    float* outB = outA + (size_t)OW_ * OCH_;   // row 2w+1
#pragma unroll
    for (int t = 0; t < 13; ++t) {
        int ch0 = 8 * t + 2 * tig;
        if (ch0 < 100) {
            float2 bo = *reinterpret_cast<const float2*>(b_off + ch0);
            *reinterpret_cast<float2*>(outA + ch0) =
                make_float2(cacc[t][0] + bo.x, cacc[t][1] + bo.y);
            *reinterpret_cast<float2*>(outB + ch0) =
                make_float2(cacc[t][2] + bo.x, cacc[t][3] + bo.y);
        }
    }
}

// ---------------------------------------------------------------------------
// Kernel B v6 (unchanged, 240us): occupancy-first.
// Tile 4y x 8x = 32 px, 128 threads, grid 1800, smem 17 KB, 64 regs ->
// 8 blocks/SM (32 warps).
// ---------------------------------------------------------------------------
#define SS_P2  34                 // c-row stride (32 px + 2 pad, even)
#define SS_Gb  (32 * SS_P2 + 8)   // 1096: group stride
#define SS_SZ  (2 * SS_Gb)        // 2192 floats

__global__ __launch_bounds__(128, 8)
void dcn_kernel(const float* __restrict__ vol,
                const float* __restrict__ w_dcn,
                const float* __restrict__ b_dcn,
                float* __restrict__ out)
{
    __shared__ __align__(16) float Ss[SS_SZ];    // 8.8 KB
    __shared__ __align__(16) float wks[2048];    // 8.2 KB

    const int tid  = threadIdx.x;
    const int lane = tid & 31;
    const int warp = tid >> 5;
    const int ox0 = blockIdx.x * 8;
    const int oy0 = blockIdx.y * 4;
    const int b   = blockIdx.z;

    const int oh = warp & 1;
    const int ph = warp >> 1;
    const int oi = lane >> 3;
    const int pj = lane & 7;
    const int o0 = 32 * oh + 8 * oi;

    const int q = lane >> 3;
    const int j = lane & 7;
    const int sBase = warp * 16;

    const float* volb = vol + (size_t)b * (H_ * W_ * C_);
    const float* offb = g_offbuf + ((size_t)(b * OH_ + oy0) * OW_ + ox0) * OCH_;

    u64t acc2[4][2];
#pragma unroll
    for (int t = 0; t < 4; ++t) {
        acc2[t][0] = 0ull; acc2[t][1] = 0ull;
    }

    for (int k = 0; k < 25; ++k) {
        __syncthreads();

        {
            const float4* wsrc = reinterpret_cast<const float4*>(w_dcn + k * 2048);
            float4* wdst = reinterpret_cast<float4*>(wks);
#pragma unroll
            for (int i = 0; i < 4; ++i)
                wdst[tid + i * 128] = wsrc[tid + i * 128];
        }

        const int fy = k / 5, fx = k - fy * 5;
        const float dky = (float)((fy - 2) * 2);
        const float dkx = (float)((fx - 2) * 2);

#pragma unroll
        for (int pass = 0; pass < 4; ++pass) {
            int s = sBase + pass * 4 + q;
            int p = s & 31, g2 = s >> 5;
            int pyi = p >> 3, pxi = p & 7;

            float4 ov = __ldg(reinterpret_cast<const float4*>(
                offb + (pyi * OW_ + pxi) * OCH_ + k * 4));
            float offy = g2 ? ov.y : ov.x;
            float offx = g2 ? ov.w : ov.z;

            float py = (float)(oy0 + pyi + 4) + dky + offy;
            float px = (float)(ox0 + pxi + 4) + dkx + offx;
            py = fminf(fmaxf(py, 0.0f), 127.0f);
            px = fminf(fmaxf(px, 0.0f), 127.0f);
            float y0f = fminf(floorf(py), 126.0f);
            float x0f = fminf(floorf(px), 126.0f);
            float wy = py - y0f, wx = px - x0f;
            int y0 = (int)y0f, x0 = (int)x0f;

            const float4* r0 = reinterpret_cast<const float4*>(
                volb + ((size_t)(y0 * W_ + x0)) * C_);
            f4u L0, L1, L2, L3;
            L0.f = r0[j];
            L1.f = r0[j + 8];
            L2.f = r0[j + 1024];
            L3.f = r0[j + 1032];

            u64t c00p = dup2((1.0f - wy) * (1.0f - wx));
            u64t c01p = dup2((1.0f - wy) * wx);
            u64t c10p = dup2(wy * (1.0f - wx));
            u64t c11p = dup2(wy * wx);

            ulonglong2 svu;
            svu.x = ffma2(L0.u.x, c00p, ffma2(L1.u.x, c01p,
                        ffma2(L2.u.x, c10p, fmul2(L3.u.x, c11p))));
            svu.y = ffma2(L0.u.y, c00p, ffma2(L1.u.y, c01p,
                        ffma2(L2.u.y, c10p, fmul2(L3.u.y, c11p))));
            float2 s01 = up2(svu.x);
            float2 s23 = up2(svu.y);

            float* dstb = &Ss[g2 * SS_Gb + p];
            dstb[(4 * j    ) * SS_P2] = s01.x;
            dstb[(4 * j + 1) * SS_P2] = s01.y;
            dstb[(4 * j + 2) * SS_P2] = s23.x;
            dstb[(4 * j + 3) * SS_P2] = s23.y;
        }
        __syncthreads();

        const float* Sg = Ss + oh * SS_Gb + 16 * ph + 2 * pj;
        const float* wo = wks + o0;
#pragma unroll 8
        for (int c = 0; c < 32; ++c) {
            f4u W0, W1;
            W0.f = *reinterpret_cast<const float4*>(wo + c * 64);
            W1.f = *reinterpret_cast<const float4*>(wo + c * 64 + 4);
            u64t wp[4] = {W0.u.x, W0.u.y, W1.u.x, W1.u.y};
            float2 sa = *reinterpret_cast<const float2*>(Sg + c * SS_P2);
            u64t b0 = dup2(sa.x);
            u64t b1 = dup2(sa.y);
#pragma unroll
            for (int t = 0; t < 4; ++t) {
                acc2[t][0] = ffma2(wp[t], b0, acc2[t][0]);
                acc2[t][1] = ffma2(wp[t], b1, acc2[t][1]);
            }
        }
    }

    f4u B0, B1;
    B0.f = __ldg(reinterpret_cast<const float4*>(b_dcn + o0));
    B1.f = __ldg(reinterpret_cast<const float4*>(b_dcn + o0 + 4));
    float bo[8];
    {
        float2 t0 = up2(B0.u.x), t1 = up2(B0.u.y), t2 = up2(B1.u.x), t3 = up2(B1.u.y);
        bo[0]=t0.x; bo[1]=t0.y; bo[2]=t1.x; bo[3]=t1.y;
        bo[4]=t2.x; bo[5]=t2.y; bo[6]=t3.x; bo[7]=t3.y;
    }
#pragma unroll
    for (int jj = 0; jj < 2; ++jj) {
        int p  = 16 * ph + 2 * pj + jj;
        int oy = oy0 + (p >> 3), ox = ox0 + (p & 7);
        float* opx = out + ((size_t)((b * OH_ + oy) * OW_ + ox)) * F_ + o0;
        float2 p0 = up2(acc2[0][jj]);
        float2 p1 = up2(acc2[1][jj]);
        float2 p2 = up2(acc2[2][jj]);
        float2 p3 = up2(acc2[3][jj]);
        float4 r0 = make_float4(p0.x + bo[0], p0.y + bo[1], p1.x + bo[2], p1.y + bo[3]);
        float4 r1 = make_float4(p2.x + bo[4], p2.y + bo[5], p3.x + bo[6], p3.y + bo[7]);
        *reinterpret_cast<float4*>(opx)     = r0;
        *reinterpret_cast<float4*>(opx + 4) = r1;
    }
}

// ---------------------------------------------------------------------------
extern "C" void kernel_launch(void* const* d_in, const int* in_sizes, int n_in,
                              void* d_out, int out_size)
{
    const float* vol   = (const float*)d_in[0];
    const float* w_off = (const float*)d_in[1];
    const float* b_off = (const float*)d_in[2];
    const float* w_dcn = (const float*)d_in[3];
    const float* b_dcn = (const float*)d_in[4];
    float* out = (float*)d_out;

    pack_woff_kernel<<<(25 * 4 * 13 * 32 * 2 + 255) / 256, 256>>>(w_off);

    dim3 gA(OW_ / 8, OH_ / 8, B_);   // (15, 15, 4)
    offset_conv_kernel<<<gA, 128>>>(vol, b_off);

    dim3 gB(OW_ / 8, OH_ / 4, B_);   // (15, 30, 4) = 1800 blocks
    dcn_kernel<<<gB, 128>>>(vol, w_dcn, b_dcn, out);
}

// round 11
// speedup vs baseline: 2.9244x; 1.4612x over previous
#include <cuda_runtime.h>

// Problem constants
#define H_   128
#define W_   128
#define C_   32
#define B_   4
#define OH_  120
#define OW_  120
#define OCH_ 100
#define F_   64

__device__ float g_offbuf[(size_t)B_ * OH_ * OW_ * OCH_];
// tf32 fragment-ordered offset-conv weights: [k][s][t13][lane][r]
__device__ unsigned g_bpack[25 * 4 * 13 * 32 * 2];      // 83200
// tf32 fragment-ordered dcn weights: [k][g][s][t4][lane][r]
__device__ unsigned g_wdpack[25 * 2 * 4 * 4 * 32 * 2];  // 51200

// ---- packed f32x2 helpers --------------------------------------------------
typedef unsigned long long u64t;

__device__ __forceinline__ u64t ffma2(u64t a, u64t b, u64t c) {
    u64t d;
    asm("fma.rn.f32x2 %0, %1, %2, %3;" : "=l"(d) : "l"(a), "l"(b), "l"(c));
    return d;
}
__device__ __forceinline__ u64t fmul2(u64t a, u64t b) {
    u64t d;
    asm("mul.rn.f32x2 %0, %1, %2;" : "=l"(d) : "l"(a), "l"(b));
    return d;
}
__device__ __forceinline__ u64t dup2(float x) {
    u64t d; unsigned xi = __float_as_uint(x);
    asm("mov.b64 %0, {%1, %1};" : "=l"(d) : "r"(xi));
    return d;
}
__device__ __forceinline__ float2 up2(u64t v) {
    float2 f;
    asm("mov.b64 {%0, %1}, %2;" : "=f"(f.x), "=f"(f.y) : "l"(v));
    return f;
}
union f4u { float4 f; ulonglong2 u; };

__device__ __forceinline__ unsigned f2tf32(float x) {
    unsigned r;
    asm("cvt.rna.tf32.f32 %0, %1;" : "=r"(r) : "f"(x));
    return r;
}

// ---------------------------------------------------------------------------
// Prepass: pack BOTH weight tensors into tf32 mma B-fragment order.
// B-frag (m16n8k8 row.col): b0 = W[K=8s+tig][N=8t+g8], b1 = K+4.
// ---------------------------------------------------------------------------
#define NPACK_OFF (25 * 4 * 13 * 32 * 2)
#define NPACK_DCN (25 * 2 * 4 * 4 * 32 * 2)

__global__ void pack_weights_kernel(const float* __restrict__ w_off,
                                    const float* __restrict__ w_dcn)
{
    int idx = blockIdx.x * 256 + threadIdx.x;
    if (idx < NPACK_OFF) {
        int r    = idx & 1;
        int lane = (idx >> 1) & 31;
        int rem  = idx >> 6;
        int t    = rem % 13;
        int s    = (rem / 13) % 4;
        int k    = rem / (13 * 4);
        int tig  = lane & 3;
        int g8   = lane >> 2;
        int c    = 8 * s + tig + 4 * r;
        int ch   = 8 * t + g8;
        float v  = (ch < 100) ? w_off[k * 3200 + c * 100 + ch] : 0.0f;
        g_bpack[idx] = f2tf32(v);
    } else if (idx < NPACK_OFF + NPACK_DCN) {
        int j    = idx - NPACK_OFF;
        int r    = j & 1;
        int lane = (j >> 1) & 31;
        int rem  = j >> 6;
        int t    = rem % 4;
        int s    = (rem / 4) % 4;
        int g    = (rem / 16) % 2;
        int k    = rem / 32;
        int tig  = lane & 3;
        int g8   = lane >> 2;
        int c    = 8 * s + tig + 4 * r;
        int o    = 32 * g + 8 * t + g8;
        g_wdpack[j] = f2tf32(w_dcn[k * 2048 + c * 64 + o]);
    }
}

// ---------------------------------------------------------------------------
// Kernel A v8 (unchanged, ~60us): offset conv via tf32 mma.sync.m16n8k8.
// ---------------------------------------------------------------------------
#define PXS 36   // pixel stride in patch (floats)

__global__ __launch_bounds__(128, 5)
void offset_conv_kernel(const float* __restrict__ vol,
                        const float* __restrict__ b_off)
{
    __shared__ float patch[16 * 16 * PXS];   // 36.9 KB

    const int tid  = threadIdx.x;
    const int lane = tid & 31;
    const int warp = tid >> 5;
    const int ox0 = blockIdx.x * 8;
    const int oy0 = blockIdx.y * 8;
    const int b   = blockIdx.z;

    for (int idx = tid; idx < 2048; idx += 128) {
        int row = idx >> 7;
        int rem = idx & 127;
        int col = rem >> 3;
        int c4  = rem & 7;
        const float4 v = *reinterpret_cast<const float4*>(
            vol + ((size_t)((b * H_ + oy0 + row) * W_ + ox0 + col)) * C_ + 4 * c4);
        *reinterpret_cast<float4*>(&patch[(row * 16 + col) * PXS + 4 * c4]) = v;
    }
    __syncthreads();

    const int g   = lane >> 2;
    const int tig = lane & 3;

    float cacc[13][4];
#pragma unroll
    for (int t = 0; t < 13; ++t)
#pragma unroll
        for (int i = 0; i < 4; ++i) cacc[t][i] = 0.0f;

    const unsigned* bp = g_bpack + 2 * lane;

#pragma unroll 1
    for (int k = 0; k < 25; ++k) {
        const int fy2 = (k / 5) * 2, fx2 = (k % 5) * 2;
        const float* pa0 = &patch[((2 * warp + fy2) * 16 + fx2 + g) * PXS];
        const float* pa1 = pa0 + 16 * PXS;

#pragma unroll
        for (int s = 0; s < 4; ++s) {
            unsigned a0 = f2tf32(pa0[8 * s + tig]);
            unsigned a1 = f2tf32(pa1[8 * s + tig]);
            unsigned a2 = f2tf32(pa0[8 * s + tig + 4]);
            unsigned a3 = f2tf32(pa1[8 * s + tig + 4]);
            const uint2* bks = reinterpret_cast<const uint2*>(
                bp + ((k * 4 + s) * 13) * 64);
#pragma unroll
            for (int t = 0; t < 13; ++t) {
                uint2 bb = __ldg(bks + t * 32);
                asm volatile(
                    "mma.sync.aligned.m16n8k8.row.col.f32.tf32.tf32.f32 "
                    "{%0,%1,%2,%3}, {%4,%5,%6,%7}, {%8,%9}, {%0,%1,%2,%3};"
                    : "+f"(cacc[t][0]), "+f"(cacc[t][1]),
                      "+f"(cacc[t][2]), "+f"(cacc[t][3])
                    : "r"(a0), "r"(a1), "r"(a2), "r"(a3),
                      "r"(bb.x), "r"(bb.y));
            }
        }
    }

    const int oyA = oy0 + 2 * warp;
    const int oxA = ox0 + g;
    float* outA = &g_offbuf[((size_t)((b * OH_ + oyA) * OW_ + oxA)) * OCH_];
    float* outB = outA + (size_t)OW_ * OCH_;
#pragma unroll
    for (int t = 0; t < 13; ++t) {
        int ch0 = 8 * t + 2 * tig;
        if (ch0 < 100) {
            float2 bo = *reinterpret_cast<const float2*>(b_off + ch0);
            *reinterpret_cast<float2*>(outA + ch0) =
                make_float2(cacc[t][0] + bo.x, cacc[t][1] + bo.y);
            *reinterpret_cast<float2*>(outB + ch0) =
                make_float2(cacc[t][2] + bo.x, cacc[t][3] + bo.y);
        }
    }
}

// ---------------------------------------------------------------------------
// Kernel B v7: gather (R8 structure) + tf32 MMA GEMM.
// Tile 4y x 8x = 32 px, 128 threads, grid 1800. Double-buffered sample smem
// [g][px][c] (px stride 36) = A-operand layout; 1 sync/tap.
// Warp = (group g, M-half mh): per tap 4 k-steps x 4 n-tiles = 16 MMAs.
// ---------------------------------------------------------------------------
#define GST (32 * PXS + 8)    // 1160: group stride in Ss

__global__ __launch_bounds__(128, 8)
void dcn_kernel(const float* __restrict__ vol,
                const float* __restrict__ b_dcn,
                float* __restrict__ out)
{
    __shared__ __align__(16) float Ss[2][2 * GST];   // 18.6 KB

    const int tid  = threadIdx.x;
    const int lane = tid & 31;
    const int warp = tid >> 5;
    const int ox0 = blockIdx.x * 8;
    const int oy0 = blockIdx.y * 4;
    const int b   = blockIdx.z;

    // GEMM roles: warp = (group, M-half); lane = (g8, tig)
    const int gw  = warp >> 1;     // group: outs 32gw..+31, samples Ss[gw]
    const int mh  = warp & 1;      // px rows 16mh..+15
    const int g8  = lane >> 2;
    const int tig = lane & 3;

    // Gather roles: per pass, 4 samples x 8 lanes; 4 passes
    const int q = lane >> 3;
    const int j = lane & 7;
    const int sBase = warp * 16;

    const float* volb = vol + (size_t)b * (H_ * W_ * C_);
    const float* offb = g_offbuf + ((size_t)(b * OH_ + oy0) * OW_ + ox0) * OCH_;

    float cacc[4][4];   // [n-tile][frag]
#pragma unroll
    for (int t = 0; t < 4; ++t)
#pragma unroll
        for (int i = 0; i < 4; ++i) cacc[t][i] = 0.0f;

    const unsigned* wdp = g_wdpack + 2 * lane;

#pragma unroll 1
    for (int k = 0; k < 25; ++k) {
        float* Sb = Ss[k & 1];

        const int fy = k / 5, fx = k - fy * 5;
        const float dky = (float)((fy - 2) * 2);
        const float dkx = (float)((fx - 2) * 2);

        // Gather 64 samples (warp-cooperative, full-line LDG.128)
#pragma unroll
        for (int pass = 0; pass < 4; ++pass) {
            int s = sBase + pass * 4 + q;
            int p = s & 31, g2 = s >> 5;
            int pyi = p >> 3, pxi = p & 7;

            float4 ov = __ldg(reinterpret_cast<const float4*>(
                offb + (pyi * OW_ + pxi) * OCH_ + k * 4));
            float offy = g2 ? ov.y : ov.x;
            float offx = g2 ? ov.w : ov.z;

            float py = (float)(oy0 + pyi + 4) + dky + offy;
            float px = (float)(ox0 + pxi + 4) + dkx + offx;
            py = fminf(fmaxf(py, 0.0f), 127.0f);
            px = fminf(fmaxf(px, 0.0f), 127.0f);
            float y0f = fminf(floorf(py), 126.0f);
            float x0f = fminf(floorf(px), 126.0f);
            float wy = py - y0f, wx = px - x0f;
            int y0 = (int)y0f, x0 = (int)x0f;

            const float4* r0 = reinterpret_cast<const float4*>(
                volb + ((size_t)(y0 * W_ + x0)) * C_);
            f4u L0, L1, L2, L3;
            L0.f = r0[j];
            L1.f = r0[j + 8];
            L2.f = r0[j + 1024];
            L3.f = r0[j + 1032];

            u64t c00p = dup2((1.0f - wy) * (1.0f - wx));
            u64t c01p = dup2((1.0f - wy) * wx);
            u64t c10p = dup2(wy * (1.0f - wx));
            u64t c11p = dup2(wy * wx);

            ulonglong2 svu;
            svu.x = ffma2(L0.u.x, c00p, ffma2(L1.u.x, c01p,
                        ffma2(L2.u.x, c10p, fmul2(L3.u.x, c11p))));
            svu.y = ffma2(L0.u.y, c00p, ffma2(L1.u.y, c01p,
                        ffma2(L2.u.y, c10p, fmul2(L3.u.y, c11p))));

            *reinterpret_cast<ulonglong2*>(&Sb[g2 * GST + p * PXS + 4 * j]) = svu;
        }
        __syncthreads();

        // GEMM via tf32 MMA: M=16 px, N=32 out (4 n-tiles), K=32 (4 steps)
        const float* Sg  = Sb + gw * GST + (16 * mh + g8) * PXS;
        const float* Sg8 = Sg + 8 * PXS;
        const unsigned* wk = wdp + ((k * 2 + gw) * 16) * 64;
#pragma unroll
        for (int s = 0; s < 4; ++s) {
            unsigned a0 = f2tf32(Sg [8 * s + tig]);
            unsigned a1 = f2tf32(Sg8[8 * s + tig]);
            unsigned a2 = f2tf32(Sg [8 * s + tig + 4]);
            unsigned a3 = f2tf32(Sg8[8 * s + tig + 4]);
            const uint2* bks = reinterpret_cast<const uint2*>(wk + (s * 4) * 64);
#pragma unroll
            for (int t = 0; t < 4; ++t) {
                uint2 bb = __ldg(bks + t * 32);
                asm volatile(
                    "mma.sync.aligned.m16n8k8.row.col.f32.tf32.tf32.f32 "
                    "{%0,%1,%2,%3}, {%4,%5,%6,%7}, {%8,%9}, {%0,%1,%2,%3};"
                    : "+f"(cacc[t][0]), "+f"(cacc[t][1]),
                      "+f"(cacc[t][2]), "+f"(cacc[t][3])
                    : "r"(a0), "r"(a1), "r"(a2), "r"(a3),
                      "r"(bb.x), "r"(bb.y));
            }
        }
    }

    // Epilogue: C rows = px 16mh+g8 (+8), cols = out 32gw+8t+2tig (+1)
    const int pA = 16 * mh + g8;
    const int pB = pA + 8;
    const int oyA = oy0 + (pA >> 3), oxA = ox0 + (pA & 7);
    const int oyB = oy0 + (pB >> 3), oxB = ox0 + (pB & 7);
    float* outA = out + ((size_t)((b * OH_ + oyA) * OW_ + oxA)) * F_;
    float* outB = out + ((size_t)((b * OH_ + oyB) * OW_ + oxB)) * F_;
#pragma unroll
    for (int t = 0; t < 4; ++t) {
        int o0 = 32 * gw + 8 * t + 2 * tig;
        float2 bo = __ldg(reinterpret_cast<const float2*>(b_dcn + o0));
        *reinterpret_cast<float2*>(outA + o0) =
            make_float2(cacc[t][0] + bo.x, cacc[t][1] + bo.y);
        *reinterpret_cast<float2*>(outB + o0) =
            make_float2(cacc[t][2] + bo.x, cacc[t][3] + bo.y);
    }
}

// ---------------------------------------------------------------------------
extern "C" void kernel_launch(void* const* d_in, const int* in_sizes, int n_in,
                              void* d_out, int out_size)
{
    const float* vol   = (const float*)d_in[0];
    const float* w_off = (const float*)d_in[1];
    const float* b_off = (const float*)d_in[2];
    const float* w_dcn = (const float*)d_in[3];
    const float* b_dcn = (const float*)d_in[4];
    float* out = (float*)d_out;

    pack_weights_kernel<<<(NPACK_OFF + NPACK_DCN + 255) / 256, 256>>>(w_off, w_dcn);

    dim3 gA(OW_ / 8, OH_ / 8, B_);   // (15, 15, 4)
    offset_conv_kernel<<<gA, 128>>>(vol, b_off);

    dim3 gB(OW_ / 8, OH_ / 4, B_);   // (15, 30, 4) = 1800 blocks
    dcn_kernel<<<gB, 128>>>(vol, b_dcn, out);
}

// round 12
// speedup vs baseline: 3.1476x; 1.0763x over previous
#include <cuda_runtime.h>

// Problem constants
#define H_   128
#define W_   128
#define C_   32
#define B_   4
#define OH_  120
#define OW_  120
#define OCH_ 100
#define F_   64

__device__ float g_offbuf[(size_t)B_ * OH_ * OW_ * OCH_];
// tf32 fragment-ordered offset-conv weights: [k][s][t13][lane][r]
__device__ unsigned g_bpack[25 * 4 * 13 * 32 * 2];      // 83200
// tf32 fragment-ordered dcn weights: [k][g][s][t4][lane][r]
__device__ unsigned g_wdpack[25 * 2 * 4 * 4 * 32 * 2];  // 51200

// ---- packed f32x2 helpers --------------------------------------------------
typedef unsigned long long u64t;

__device__ __forceinline__ u64t ffma2(u64t a, u64t b, u64t c) {
    u64t d;
    asm("fma.rn.f32x2 %0, %1, %2, %3;" : "=l"(d) : "l"(a), "l"(b), "l"(c));
    return d;
}
__device__ __forceinline__ u64t fmul2(u64t a, u64t b) {
    u64t d;
    asm("mul.rn.f32x2 %0, %1, %2;" : "=l"(d) : "l"(a), "l"(b));
    return d;
}
__device__ __forceinline__ u64t dup2(float x) {
    u64t d; unsigned xi = __float_as_uint(x);
    asm("mov.b64 %0, {%1, %1};" : "=l"(d) : "r"(xi));
    return d;
}
__device__ __forceinline__ float2 up2(u64t v) {
    float2 f;
    asm("mov.b64 {%0, %1}, %2;" : "=f"(f.x), "=f"(f.y) : "l"(v));
    return f;
}
union f4u { float4 f; ulonglong2 u; };

__device__ __forceinline__ unsigned f2tf32(float x) {
    unsigned r;
    asm("cvt.rna.tf32.f32 %0, %1;" : "=r"(r) : "f"(x));
    return r;
}

// ---------------------------------------------------------------------------
// Prepass: pack BOTH weight tensors into tf32 mma B-fragment order.
// ---------------------------------------------------------------------------
#define NPACK_OFF (25 * 4 * 13 * 32 * 2)
#define NPACK_DCN (25 * 2 * 4 * 4 * 32 * 2)

__global__ void pack_weights_kernel(const float* __restrict__ w_off,
                                    const float* __restrict__ w_dcn)
{
    int idx = blockIdx.x * 256 + threadIdx.x;
    if (idx < NPACK_OFF) {
        int r    = idx & 1;
        int lane = (idx >> 1) & 31;
        int rem  = idx >> 6;
        int t    = rem % 13;
        int s    = (rem / 13) % 4;
        int k    = rem / (13 * 4);
        int tig  = lane & 3;
        int g8   = lane >> 2;
        int c    = 8 * s + tig + 4 * r;
        int ch   = 8 * t + g8;
        float v  = (ch < 100) ? w_off[k * 3200 + c * 100 + ch] : 0.0f;
        g_bpack[idx] = f2tf32(v);
    } else if (idx < NPACK_OFF + NPACK_DCN) {
        int j    = idx - NPACK_OFF;
        int r    = j & 1;
        int lane = (j >> 1) & 31;
        int rem  = j >> 6;
        int t    = rem % 4;
        int s    = (rem / 4) % 4;
        int g    = (rem / 16) % 2;
        int k    = rem / 32;
        int tig  = lane & 3;
        int g8   = lane >> 2;
        int c    = 8 * s + tig + 4 * r;
        int o    = 32 * g + 8 * t + g8;
        g_wdpack[j] = f2tf32(w_dcn[k * 2048 + c * 64 + o]);
    }
}

// ---------------------------------------------------------------------------
// Kernel A v8 (unchanged, ~60us): offset conv via tf32 mma.sync.m16n8k8.
// ---------------------------------------------------------------------------
#define PXS 36   // pixel stride in patch (floats)

__global__ __launch_bounds__(128, 5)
void offset_conv_kernel(const float* __restrict__ vol,
                        const float* __restrict__ b_off)
{
    __shared__ float patch[16 * 16 * PXS];   // 36.9 KB

    const int tid  = threadIdx.x;
    const int lane = tid & 31;
    const int warp = tid >> 5;
    const int ox0 = blockIdx.x * 8;
    const int oy0 = blockIdx.y * 8;
    const int b   = blockIdx.z;

    for (int idx = tid; idx < 2048; idx += 128) {
        int row = idx >> 7;
        int rem = idx & 127;
        int col = rem >> 3;
        int c4  = rem & 7;
        const float4 v = *reinterpret_cast<const float4*>(
            vol + ((size_t)((b * H_ + oy0 + row) * W_ + ox0 + col)) * C_ + 4 * c4);
        *reinterpret_cast<float4*>(&patch[(row * 16 + col) * PXS + 4 * c4]) = v;
    }
    __syncthreads();

    const int g   = lane >> 2;
    const int tig = lane & 3;

    float cacc[13][4];
#pragma unroll
    for (int t = 0; t < 13; ++t)
#pragma unroll
        for (int i = 0; i < 4; ++i) cacc[t][i] = 0.0f;

    const unsigned* bp = g_bpack + 2 * lane;

#pragma unroll 1
    for (int k = 0; k < 25; ++k) {
        const int fy2 = (k / 5) * 2, fx2 = (k % 5) * 2;
        const float* pa0 = &patch[((2 * warp + fy2) * 16 + fx2 + g) * PXS];
        const float* pa1 = pa0 + 16 * PXS;

#pragma unroll
        for (int s = 0; s < 4; ++s) {
            unsigned a0 = f2tf32(pa0[8 * s + tig]);
            unsigned a1 = f2tf32(pa1[8 * s + tig]);
            unsigned a2 = f2tf32(pa0[8 * s + tig + 4]);
            unsigned a3 = f2tf32(pa1[8 * s + tig + 4]);
            const uint2* bks = reinterpret_cast<const uint2*>(
                bp + ((k * 4 + s) * 13) * 64);
#pragma unroll
            for (int t = 0; t < 13; ++t) {
                uint2 bb = __ldg(bks + t * 32);
                asm volatile(
                    "mma.sync.aligned.m16n8k8.row.col.f32.tf32.tf32.f32 "
                    "{%0,%1,%2,%3}, {%4,%5,%6,%7}, {%8,%9}, {%0,%1,%2,%3};"
                    : "+f"(cacc[t][0]), "+f"(cacc[t][1]),
                      "+f"(cacc[t][2]), "+f"(cacc[t][3])
                    : "r"(a0), "r"(a1), "r"(a2), "r"(a3),
                      "r"(bb.x), "r"(bb.y));
            }
        }
    }

    const int oyA = oy0 + 2 * warp;
    const int oxA = ox0 + g;
    float* outA = &g_offbuf[((size_t)((b * OH_ + oyA) * OW_ + oxA)) * OCH_];
    float* outB = outA + (size_t)OW_ * OCH_;
#pragma unroll
    for (int t = 0; t < 13; ++t) {
        int ch0 = 8 * t + 2 * tig;
        if (ch0 < 100) {
            float2 bo = *reinterpret_cast<const float2*>(b_off + ch0);
            *reinterpret_cast<float2*>(outA + ch0) =
                make_float2(cacc[t][0] + bo.x, cacc[t][1] + bo.y);
            *reinterpret_cast<float2*>(outB + ch0) =
                make_float2(cacc[t][2] + bo.x, cacc[t][3] + bo.y);
        }
    }
}

// ---------------------------------------------------------------------------
// Kernel B v8: gather + tf32 MMA GEMM, with smem-staged offsets and tf32
// conversion moved into the gather.
// Tile 4y x 8x = 32 px, 128 threads, grid 1800. Double-buffered sample smem
// [g][px][c] (px stride 36, tf32 bits); 1 sync/tap; offsets staged once.
// ---------------------------------------------------------------------------
#define GST (32 * PXS + 8)    // 1160: group stride in Ss
#define OFS 104               // offset row stride (floats, 16B-aligned)

__global__ __launch_bounds__(128, 7)
void dcn_kernel(const float* __restrict__ vol,
                const float* __restrict__ b_dcn,
                float* __restrict__ out)
{
    __shared__ __align__(16) float Ss[2][2 * GST];   // 18.6 KB (tf32 bits)
    __shared__ __align__(16) float offS[32 * OFS];   // 13.3 KB

    const int tid  = threadIdx.x;
    const int lane = tid & 31;
    const int warp = tid >> 5;
    const int ox0 = blockIdx.x * 8;
    const int oy0 = blockIdx.y * 4;
    const int b   = blockIdx.z;

    // GEMM roles
    const int gw  = warp >> 1;
    const int mh  = warp & 1;
    const int g8  = lane >> 2;
    const int tig = lane & 3;

    // Gather roles
    const int q = lane >> 3;
    const int j = lane & 7;
    const int sBase = warp * 16;

    const float* volb = vol + (size_t)b * (H_ * W_ * C_);
    const float* offb = g_offbuf + ((size_t)(b * OH_ + oy0) * OW_ + ox0) * OCH_;

    // Stage the tile's 32x100 offsets once (L2 -> smem)
    for (int idx = tid; idx < 3200; idx += 128) {
        int p  = idx / 100;
        int ch = idx - p * 100;
        int pyi = p >> 3, pxi = p & 7;
        offS[p * OFS + ch] = __ldg(offb + (pyi * OW_ + pxi) * OCH_ + ch);
    }
    __syncthreads();

    float cacc[4][4];
#pragma unroll
    for (int t = 0; t < 4; ++t)
#pragma unroll
        for (int i = 0; i < 4; ++i) cacc[t][i] = 0.0f;

    const unsigned* wdp = g_wdpack + 2 * lane;

#pragma unroll 1
    for (int k = 0; k < 25; ++k) {
        float* Sb = Ss[k & 1];

        const int fy = k / 5, fx = k - fy * 5;
        const float dky = (float)((fy - 2) * 2);
        const float dkx = (float)((fx - 2) * 2);

        // Gather 64 samples (warp-cooperative, full-line LDG.128)
#pragma unroll
        for (int pass = 0; pass < 4; ++pass) {
            int s = sBase + pass * 4 + q;
            int p = s & 31, g2 = s >> 5;
            int pyi = p >> 3, pxi = p & 7;

            // offsets from smem (LDS, ~29 cyc instead of L2 LDG ~234)
            float4 ov = *reinterpret_cast<const float4*>(&offS[p * OFS + 4 * k]);
            float offy = g2 ? ov.y : ov.x;
            float offx = g2 ? ov.w : ov.z;

            float py = (float)(oy0 + pyi + 4) + dky + offy;
            float px = (float)(ox0 + pxi + 4) + dkx + offx;
            py = fminf(fmaxf(py, 0.0f), 127.0f);
            px = fminf(fmaxf(px, 0.0f), 127.0f);
            float y0f = fminf(floorf(py), 126.0f);
            float x0f = fminf(floorf(px), 126.0f);
            float wy = py - y0f, wx = px - x0f;
            int y0 = (int)y0f, x0 = (int)x0f;

            const float4* r0 = reinterpret_cast<const float4*>(
                volb + ((size_t)(y0 * W_ + x0)) * C_);
            f4u L0, L1, L2, L3;
            L0.f = r0[j];
            L1.f = r0[j + 8];
            L2.f = r0[j + 1024];
            L3.f = r0[j + 1032];

            u64t c00p = dup2((1.0f - wy) * (1.0f - wx));
            u64t c01p = dup2((1.0f - wy) * wx);
            u64t c10p = dup2(wy * (1.0f - wx));
            u64t c11p = dup2(wy * wx);

            ulonglong2 svu;
            svu.x = ffma2(L0.u.x, c00p, ffma2(L1.u.x, c01p,
                        ffma2(L2.u.x, c10p, fmul2(L3.u.x, c11p))));
            svu.y = ffma2(L0.u.y, c00p, ffma2(L1.u.y, c01p,
                        ffma2(L2.u.y, c10p, fmul2(L3.u.y, c11p))));
            float2 s01 = up2(svu.x);
            float2 s23 = up2(svu.y);

            // convert to tf32 here; GEMM A-frag becomes a bare LDS.32
            uint4 sv;
            sv.x = f2tf32(s01.x);
            sv.y = f2tf32(s01.y);
            sv.z = f2tf32(s23.x);
            sv.w = f2tf32(s23.y);
            *reinterpret_cast<uint4*>(&Sb[g2 * GST + p * PXS + 4 * j]) = sv;
        }
        __syncthreads();

        // GEMM via tf32 MMA: M=16 px, N=32 out (4 n-tiles), K=32 (4 steps)
        const unsigned* Sg  = reinterpret_cast<const unsigned*>(
            Sb + gw * GST + (16 * mh + g8) * PXS);
        const unsigned* Sg8 = Sg + 8 * PXS;
        const unsigned* wk = wdp + ((k * 2 + gw) * 16) * 64;
#pragma unroll
        for (int s = 0; s < 4; ++s) {
            unsigned a0 = Sg [8 * s + tig];
            unsigned a1 = Sg8[8 * s + tig];
            unsigned a2 = Sg [8 * s + tig + 4];
            unsigned a3 = Sg8[8 * s + tig + 4];
            const uint2* bks = reinterpret_cast<const uint2*>(wk + (s * 4) * 64);
#pragma unroll
            for (int t = 0; t < 4; ++t) {
                uint2 bb = __ldg(bks + t * 32);
                asm volatile(
                    "mma.sync.aligned.m16n8k8.row.col.f32.tf32.tf32.f32 "
                    "{%0,%1,%2,%3}, {%4,%5,%6,%7}, {%8,%9}, {%0,%1,%2,%3};"
                    : "+f"(cacc[t][0]), "+f"(cacc[t][1]),
                      "+f"(cacc[t][2]), "+f"(cacc[t][3])
                    : "r"(a0), "r"(a1), "r"(a2), "r"(a3),
                      "r"(bb.x), "r"(bb.y));
            }
        }
    }

    // Epilogue: C rows = px 16mh+g8 (+8), cols = out 32gw+8t+2tig (+1)
    const int pA = 16 * mh + g8;
    const int pB = pA + 8;
    const int oyA = oy0 + (pA >> 3), oxA = ox0 + (pA & 7);
    const int oyB = oy0 + (pB >> 3), oxB = ox0 + (pB & 7);
    float* outA = out + ((size_t)((b * OH_ + oyA) * OW_ + oxA)) * F_;
    float* outB = out + ((size_t)((b * OH_ + oyB) * OW_ + oxB)) * F_;
#pragma unroll
    for (int t = 0; t < 4; ++t) {
        int o0 = 32 * gw + 8 * t + 2 * tig;
        float2 bo = __ldg(reinterpret_cast<const float2*>(b_dcn + o0));
        *reinterpret_cast<float2*>(outA + o0) =
            make_float2(cacc[t][0] + bo.x, cacc[t][1] + bo.y);
        *reinterpret_cast<float2*>(outB + o0) =
            make_float2(cacc[t][2] + bo.x, cacc[t][3] + bo.y);
    }
}

// ---------------------------------------------------------------------------
extern "C" void kernel_launch(void* const* d_in, const int* in_sizes, int n_in,
                              void* d_out, int out_size)
{
    const float* vol   = (const float*)d_in[0];
    const float* w_off = (const float*)d_in[1];
    const float* b_off = (const float*)d_in[2];
    const float* w_dcn = (const float*)d_in[3];
    const float* b_dcn = (const float*)d_in[4];
    float* out = (float*)d_out;

    pack_weights_kernel<<<(NPACK_OFF + NPACK_DCN + 255) / 256, 256>>>(w_off, w_dcn);

    dim3 gA(OW_ / 8, OH_ / 8, B_);   // (15, 15, 4)
    offset_conv_kernel<<<gA, 128>>>(vol, b_off);

    dim3 gB(OW_ / 8, OH_ / 4, B_);   // (15, 30, 4) = 1800 blocks
    dcn_kernel<<<gB, 128>>>(vol, b_dcn, out);
}